// round 14
// baseline (speedup 1.0000x reference)
#include <cuda_runtime.h>
#include <cuda_bf16.h>
#include <cuda_fp16.h>
#include <math.h>
#include <stdint.h>

// ---------------------------------------------------------------------------
// Problem constants
// ---------------------------------------------------------------------------
#define S_LEN 2048
#define D_MODEL 4096
#define N_HEADS 32
#define N_KV_HEADS 8
#define HEAD_DIM 128
#define QKV_N 6144                       // 4096 + 1024 + 1024
#define QK_SCALE 0.08838834764831845f    // 1/sqrt(128)

// ---------------------------------------------------------------------------
// Scratch (device globals; allocation is forbidden).  All fp16 now.
// ---------------------------------------------------------------------------
__device__ unsigned short g_xhi[S_LEN * D_MODEL];
__device__ unsigned short g_xlo[S_LEN * D_MODEL];
__device__ unsigned short g_wqkvT[QKV_N * D_MODEL];     // single fp16
__device__ unsigned short g_woT[D_MODEL * D_MODEL];     // single fp16
__device__ float g_qkv[S_LEN * QKV_N];
__device__ unsigned short g_qhi[S_LEN * D_MODEL];
__device__ unsigned short g_qlo[S_LEN * D_MODEL];
__device__ unsigned short g_khi[S_LEN * 1024];          // single fp16
__device__ unsigned short g_vthi[1024 * S_LEN];         // [dglob][s], fp16
__device__ unsigned short g_atthi[S_LEN * D_MODEL];
__device__ unsigned short g_attlo[S_LEN * D_MODEL];

// ---------------------------------------------------------------------------
// Baseline-PTX helpers (NO tcgen05/TMA — harness compiles for compute_103)
// ---------------------------------------------------------------------------
__device__ __forceinline__ uint32_t cvta_shared(const void* p) {
    return (uint32_t)__cvta_generic_to_shared(p);
}
__device__ __forceinline__ void cp16(uint32_t dst, const void* src) {
    asm volatile("cp.async.cg.shared.global [%0], [%1], 16;" :: "r"(dst), "l"(src) : "memory");
}
__device__ __forceinline__ void cp_commit() {
    asm volatile("cp.async.commit_group;" ::: "memory");
}
template <int N> __device__ __forceinline__ void cp_wait() {
    asm volatile("cp.async.wait_group %0;" :: "n"(N) : "memory");
}
__device__ __forceinline__ void ldsm4(uint32_t* r, uint32_t addr) {
    asm volatile("ldmatrix.sync.aligned.m8n8.x4.shared.b16 {%0,%1,%2,%3}, [%4];"
                 : "=r"(r[0]), "=r"(r[1]), "=r"(r[2]), "=r"(r[3]) : "r"(addr));
}
__device__ __forceinline__ void mma_fp16(float* c, const uint32_t* a, const uint32_t* b) {
    asm volatile(
        "mma.sync.aligned.m16n8k16.row.col.f32.f16.f16.f32 "
        "{%0,%1,%2,%3}, {%4,%5,%6,%7}, {%8,%9}, {%0,%1,%2,%3};"
        : "+f"(c[0]), "+f"(c[1]), "+f"(c[2]), "+f"(c[3])
        : "r"(a[0]), "r"(a[1]), "r"(a[2]), "r"(a[3]), "r"(b[0]), "r"(b[1]));
}
__device__ __forceinline__ uint32_t pack_h2(float lo, float hi) {
    __half2 h = __floats2half2_rn(lo, hi);
    return *(uint32_t*)&h;
}
__device__ __forceinline__ unsigned short f2h_bits(float v) {
    __half h = __float2half_rn(v);
    return *(unsigned short*)&h;
}
__device__ __forceinline__ float h_bits2f(unsigned short b) {
    __half h = *(__half*)&b;
    return __half2float(h);
}

// ---------------------------------------------------------------------------
// fp32 -> fp16 hi/lo split (elementwise, vectorized)
// ---------------------------------------------------------------------------
__global__ void split_kernel(const float* __restrict__ x,
                             unsigned short* __restrict__ hi,
                             unsigned short* __restrict__ lo, int n4) {
    int i = blockIdx.x * blockDim.x + threadIdx.x;
    if (i >= n4) return;
    float4 v = ((const float4*)x)[i];
    ushort4 hh, ll;
    hh.x = f2h_bits(v.x); ll.x = f2h_bits(v.x - h_bits2f(hh.x));
    hh.y = f2h_bits(v.y); ll.y = f2h_bits(v.y - h_bits2f(hh.y));
    hh.z = f2h_bits(v.z); ll.z = f2h_bits(v.z - h_bits2f(hh.z));
    hh.w = f2h_bits(v.w); ll.w = f2h_bits(v.w - h_bits2f(hh.w));
    ((ushort4*)hi)[i] = hh;
    ((ushort4*)lo)[i] = ll;
}

// ---------------------------------------------------------------------------
// W[K x N] fp32 -> T[N x K] single fp16 (tiled transpose)
// ---------------------------------------------------------------------------
__global__ void transpose_h_kernel(const float* __restrict__ W,
                                   unsigned short* __restrict__ T,
                                   int K, int N) {
    __shared__ float t[32][33];
    int n0 = blockIdx.x * 32, k0 = blockIdx.y * 32;
    int tx = threadIdx.x, ty = threadIdx.y;  // 32 x 8
#pragma unroll
    for (int r = 0; r < 32; r += 8)
        t[ty + r][tx] = W[(size_t)(k0 + ty + r) * N + n0 + tx];
    __syncthreads();
#pragma unroll
    for (int r = 0; r < 32; r += 8) {
        size_t o = (size_t)(n0 + ty + r) * K + k0 + tx;
        T[o] = f2h_bits(t[tx][ty + r]);
    }
}

// ---------------------------------------------------------------------------
// V region of qkv -> transposed fp16 [dglob][s]
// ---------------------------------------------------------------------------
__global__ void vsplit_transpose_kernel(const float* __restrict__ qkv,
                                        unsigned short* __restrict__ Thi) {
    __shared__ float t[32][33];
    int d0 = blockIdx.x * 32, s0 = blockIdx.y * 32;
    int tx = threadIdx.x, ty = threadIdx.y;  // 32 x 8
#pragma unroll
    for (int r = 0; r < 32; r += 8)
        t[ty + r][tx] = qkv[(size_t)(s0 + ty + r) * QKV_N + 5120 + d0 + tx];
    __syncthreads();
#pragma unroll
    for (int r = 0; r < 32; r += 8) {
        size_t o = (size_t)(d0 + ty + r) * S_LEN + s0 + tx;
        Thi[o] = f2h_bits(t[tx][ty + r]);
    }
}

// ---------------------------------------------------------------------------
// RoPE + scale; Q -> fp16 hi/lo, K -> single fp16.
// ---------------------------------------------------------------------------
__global__ void rope_split_kernel(const float* __restrict__ qkv,
                                  const float* __restrict__ cosp,
                                  const float* __restrict__ sinp,
                                  unsigned short* __restrict__ qhi,
                                  unsigned short* __restrict__ qlo,
                                  unsigned short* __restrict__ khi) {
    int idx = blockIdx.x * blockDim.x + threadIdx.x;
    const int PAIRS = (D_MODEL + 1024) / 2;  // 2560 per row
    if (idx >= S_LEN * PAIRS) return;
    int s = idx / PAIRS;
    int pair = idx - s * PAIRS;
    int p = pair & 63;
    float c = cosp[s * 64 + p];
    float sn = sinp[s * 64 + p];
    bool isQ = pair < 2048;
    int col = isQ ? 2 * pair : 4096 + 2 * (pair - 2048);
    const float* src = qkv + (size_t)s * QKV_N + col;
    float t0 = src[0], t1 = src[1];
    float o0 = t0 * c - t1 * sn;
    float o1 = t0 * sn + t1 * c;
    if (isQ) {
        o0 *= QK_SCALE; o1 *= QK_SCALE;
        ushort2 hh, ll;
        hh.x = f2h_bits(o0); ll.x = f2h_bits(o0 - h_bits2f(hh.x));
        hh.y = f2h_bits(o1); ll.y = f2h_bits(o1 - h_bits2f(hh.y));
        size_t o = (size_t)s * D_MODEL + 2 * pair;
        *(ushort2*)(qhi + o) = hh;
        *(ushort2*)(qlo + o) = ll;
    } else {
        ushort2 hh = make_ushort2(f2h_bits(o0), f2h_bits(o1));
        *(ushort2*)(khi + (size_t)s * 1024 + 2 * (pair - 2048)) = hh;
    }
}

// ---------------------------------------------------------------------------
// Warp-MMA fp16 2-pass GEMM: C[M,N] = (Ahi+Alo)[M,K] @ B[N,K]^T
// A split fp16 (22-bit combined); B single fp16 (error = fp16 rounding of B).
// CTA tile 128x128, BK=32, 8 warps, 2-stage cp.async, 2 CTAs/SM.
// ---------------------------------------------------------------------------
#define G2_BM 128
#define G2_BN 128
#define G2_BK 32
#define G2_ROWB 80
#define G2_TILE 10240
#define G2_STAGE 30720       // Ahi, Alo, B
#define G2_STAGES 2
#define G2_SMEM (G2_STAGES * G2_STAGE)

__global__ __launch_bounds__(256, 2) void gemm_mma_kernel(
    const unsigned short* __restrict__ Ahi_, const unsigned short* __restrict__ Alo_,
    const unsigned short* __restrict__ B_,
    float* __restrict__ C, int M, int N, int K)
{
    extern __shared__ char smem[];
    uint32_t sb = cvta_shared(smem);
    const int tid = threadIdx.x;
    const int lane = tid & 31, wid = tid >> 5;
    const int warp_m = wid & 3;
    const int warp_n = wid >> 2;
    const int m0 = blockIdx.x * G2_BM;
    const int n0 = blockIdx.y * G2_BN;

    const unsigned short* srcs[3] = {
        Ahi_ + (size_t)m0 * K, Alo_ + (size_t)m0 * K, B_ + (size_t)n0 * K };

    auto load_stage = [&](int ch, int st) {
        uint32_t base = sb + st * G2_STAGE;
        int k0 = ch * G2_BK;
#pragma unroll
        for (int v = 0; v < 3; v++) {
            uint32_t tb = base + v * G2_TILE;
            const unsigned short* src = srcs[v];
            for (int i = tid; i < 512; i += 256) {
                int row = i >> 2, c = i & 3;
                cp16(tb + row * G2_ROWB + c * 16,
                     src + (size_t)row * K + k0 + c * 8);
            }
        }
        cp_commit();
    };

    float acc[2][8][4];
#pragma unroll
    for (int mt = 0; mt < 2; mt++)
#pragma unroll
        for (int nt = 0; nt < 8; nt++)
#pragma unroll
            for (int r = 0; r < 4; r++) acc[mt][nt][r] = 0.f;

    const int NC = K / G2_BK;
    load_stage(0, 0);

    const uint32_t a_off = (uint32_t)((lane & 15) * G2_ROWB + (lane >> 4) * 16);

    for (int ch = 0; ch < NC; ch++) {
        int st = ch & 1;
        if (ch + 1 < NC) { load_stage(ch + 1, st ^ 1); cp_wait<1>(); }
        else { cp_wait<0>(); }
        __syncthreads();

        uint32_t base = sb + st * G2_STAGE;
        uint32_t aHi = base + (warp_m * 32) * G2_ROWB + a_off;
        uint32_t aLo = aHi + G2_TILE;
        uint32_t bT = base + 2 * G2_TILE + (warp_n * 64) * G2_ROWB + a_off;

#pragma unroll
        for (int k16 = 0; k16 < 2; k16++) {
            uint32_t koff = k16 * 32;
            uint32_t ahi[2][4], alo[2][4];
#pragma unroll
            for (int mt = 0; mt < 2; mt++) {
                ldsm4(ahi[mt], aHi + mt * 16 * G2_ROWB + koff);
                ldsm4(alo[mt], aLo + mt * 16 * G2_ROWB + koff);
            }
            uint32_t bh[8][2];
#pragma unroll
            for (int ng = 0; ng < 4; ng++) {
                uint32_t r[4];
                ldsm4(r, bT + ng * 16 * G2_ROWB + koff);
                bh[2 * ng][0] = r[0]; bh[2 * ng][1] = r[2];
                bh[2 * ng + 1][0] = r[1]; bh[2 * ng + 1][1] = r[3];
            }
#pragma unroll
            for (int mt = 0; mt < 2; mt++)
#pragma unroll
                for (int nt = 0; nt < 8; nt++) {
                    mma_fp16(acc[mt][nt], ahi[mt], bh[nt]);
                    mma_fp16(acc[mt][nt], alo[mt], bh[nt]);
                }
        }
        __syncthreads();
    }

#pragma unroll
    for (int mt = 0; mt < 2; mt++) {
        int row = m0 + warp_m * 32 + mt * 16 + (lane >> 2);
#pragma unroll
        for (int nt = 0; nt < 8; nt++) {
            int col = n0 + warp_n * 64 + nt * 8 + (lane & 3) * 2;
            *(float2*)&C[(size_t)row * N + col] =
                make_float2(acc[mt][nt][0], acc[mt][nt][1]);
            *(float2*)&C[(size_t)(row + 8) * N + col] =
                make_float2(acc[mt][nt][2], acc[mt][nt][3]);
        }
    }
}

// ---------------------------------------------------------------------------
// Tensor-core flash attention v7 (causal, GQA 4:1), all fp16 MMA.
// S = (Qhi+Qlo) @ K^T: 2-pass (Q split fp16, K single fp16).
// O += P @ V: 1-pass fp16 (proven R9).
// Structure identical to R9 (best): 128 thr, 64 q-rows, KV=32, 2-stage.
// ---------------------------------------------------------------------------
#define A7_QROW 272      // 128 halfs * 2B + 16B pad
#define A7_VROW 80       // 32 halfs * 2B + 16B pad
#define A7_QHI 0
#define A7_QLO 17408     // 64 * 272
#define A7_ST0 34816
#define A7_K 0
#define A7_V 8704        // 32 * 272
#define A7_STAGE_SZ 18944   // 8704 + 10240
#define A7_SMEM (A7_ST0 + 2 * A7_STAGE_SZ)   // 72704 B -> 2 CTAs/SM

__global__ __launch_bounds__(128, 2) void attn_mma_kernel(
    const unsigned short* __restrict__ Qhi, const unsigned short* __restrict__ Qlo,
    const unsigned short* __restrict__ Khi,
    const unsigned short* __restrict__ Vthi,
    unsigned short* __restrict__ atthi, unsigned short* __restrict__ attlo)
{
    extern __shared__ char smem[];
    uint32_t sb = cvta_shared(smem);
    const int tid = threadIdx.x;
    const int lane = tid & 31, wid = tid >> 5;          // 4 warps
    const int qblk = gridDim.x - 1 - blockIdx.x;        // heavy blocks first
    const int h = blockIdx.y;
    const int kvh = h >> 2;
    const int q0 = qblk * 64;
    const int wr = wid * 16;                            // warp rows 0..63
    const int g = lane >> 2;
    const int t4 = lane & 3;

    // ---- issue Q tile loads (once): 64 rows x 128 halfs, hi+lo ----
    {
        const unsigned short* qsrc[2] = {
            Qhi + (size_t)q0 * D_MODEL + h * 128,
            Qlo + (size_t)q0 * D_MODEL + h * 128 };
#pragma unroll
        for (int v = 0; v < 2; v++) {
            uint32_t dst = sb + (v ? A7_QLO : A7_QHI);
            for (int i = tid; i < 1024; i += 128) {
                int row = i >> 4, c = i & 15;
                cp16(dst + row * A7_QROW + c * 16,
                     qsrc[v] + (size_t)row * D_MODEL + c * 8);
            }
        }
        cp_commit();
    }

    const unsigned short* ksrc = Khi + kvh * 128;
    const unsigned short* vsrc = Vthi + (size_t)kvh * 128 * S_LEN;

    auto load_tile = [&](int j, int st) {
        uint32_t base = sb + A7_ST0 + st * A7_STAGE_SZ;
        int kv0 = j * 32;
        // K: 32 rows x 256B (fp16)
        for (int i = tid; i < 512; i += 128) {
            int row = i >> 4, c = i & 15;
            cp16(base + A7_K + row * A7_QROW + c * 16,
                 ksrc + (size_t)(kv0 + row) * 1024 + c * 8);
        }
        // V: 128 d-rows x 64B (fp16)
        for (int i = tid; i < 512; i += 128) {
            int row = i >> 2, c = i & 3;
            cp16(base + A7_V + row * A7_VROW + c * 16,
                 vsrc + (size_t)row * S_LEN + kv0 + c * 8);
        }
        cp_commit();
    };

    const int ntiles = 2 * qblk + 2;
    load_tile(0, 0);
    cp_wait<1>();          // Q group done (only tile0 outstanding)
    __syncthreads();

    // ---- hoist Q fragments into registers (16 rows x 128 K per warp) ----
    const uint32_t lmoff = (uint32_t)((lane & 15) * A7_QROW + (lane >> 4) * 16);
    uint32_t aqh[8][4], aql[8][4];
    {
        uint32_t qh = sb + A7_QHI + wr * A7_QROW + lmoff;
        uint32_t ql = sb + A7_QLO + wr * A7_QROW + lmoff;
#pragma unroll
        for (int kk = 0; kk < 8; kk++) {
            ldsm4(aqh[kk], qh + kk * 32);
            ldsm4(aql[kk], ql + kk * 32);
        }
    }

    float o[16][4];
#pragma unroll
    for (int nt = 0; nt < 16; nt++)
#pragma unroll
        for (int r = 0; r < 4; r++) o[nt][r] = 0.f;
    float m0 = -1e30f, m1 = -1e30f, l0 = 0.f, l1 = 0.f;

    const uint32_t vmoff = (uint32_t)((lane & 15) * A7_VROW + (lane >> 4) * 16);

    for (int j = 0; j < ntiles; j++) {
        int st = j & 1;
        __syncthreads();   // all warps done reading buffer st^1 (iter j-1)
        if (j + 1 < ntiles) { load_tile(j + 1, st ^ 1); cp_wait<1>(); }
        else { cp_wait<0>(); }
        __syncthreads();

        uint32_t base = sb + A7_ST0 + st * A7_STAGE_SZ;
        uint32_t kB = base + A7_K + lmoff;

        // ---- S = Q @ K^T (2-pass fp16 split-Q), 16 rows x 32 cols ----
        float sacc[4][4];
#pragma unroll
        for (int nt = 0; nt < 4; nt++)
#pragma unroll
            for (int r = 0; r < 4; r++) sacc[nt][r] = 0.f;

#pragma unroll
        for (int kk = 0; kk < 8; kk++) {
#pragma unroll
            for (int ng = 0; ng < 2; ng++) {
                uint32_t rh[4];
                ldsm4(rh, kB + ng * 16 * A7_QROW + kk * 32);
                uint32_t b0[2] = { rh[0], rh[2] }, b1[2] = { rh[1], rh[3] };
                mma_fp16(sacc[2 * ng],     aqh[kk], b0);
                mma_fp16(sacc[2 * ng],     aql[kk], b0);
                mma_fp16(sacc[2 * ng + 1], aqh[kk], b1);
                mma_fp16(sacc[2 * ng + 1], aql[kk], b1);
            }
        }

        // ---- causal mask (diagonal tiles only) ----
        if (j >= 2 * qblk) {
            int r0 = q0 + wr + g, r1 = r0 + 8;
            int cb = j * 32 + 2 * t4;
#pragma unroll
            for (int nt = 0; nt < 4; nt++) {
                int c0 = cb + nt * 8, c1 = c0 + 1;
                if (c0 > r0) sacc[nt][0] = -1e30f;
                if (c1 > r0) sacc[nt][1] = -1e30f;
                if (c0 > r1) sacc[nt][2] = -1e30f;
                if (c1 > r1) sacc[nt][3] = -1e30f;
            }
        }

        // ---- online softmax ----
        float mx0 = -1e30f, mx1 = -1e30f;
#pragma unroll
        for (int nt = 0; nt < 4; nt++) {
            mx0 = fmaxf(mx0, fmaxf(sacc[nt][0], sacc[nt][1]));
            mx1 = fmaxf(mx1, fmaxf(sacc[nt][2], sacc[nt][3]));
        }
        mx0 = fmaxf(mx0, __shfl_xor_sync(0xffffffffu, mx0, 1));
        mx0 = fmaxf(mx0, __shfl_xor_sync(0xffffffffu, mx0, 2));
        mx1 = fmaxf(mx1, __shfl_xor_sync(0xffffffffu, mx1, 1));
        mx1 = fmaxf(mx1, __shfl_xor_sync(0xffffffffu, mx1, 2));
        float mn0 = fmaxf(m0, mx0), mn1 = fmaxf(m1, mx1);
        float sc0 = __expf(m0 - mn0), sc1 = __expf(m1 - mn1);
        m0 = mn0; m1 = mn1;
        float sum0 = 0.f, sum1 = 0.f;
#pragma unroll
        for (int nt = 0; nt < 4; nt++) {
            sacc[nt][0] = __expf(sacc[nt][0] - mn0);
            sacc[nt][1] = __expf(sacc[nt][1] - mn0);
            sacc[nt][2] = __expf(sacc[nt][2] - mn1);
            sacc[nt][3] = __expf(sacc[nt][3] - mn1);
            sum0 += sacc[nt][0] + sacc[nt][1];
            sum1 += sacc[nt][2] + sacc[nt][3];
        }
        sum0 += __shfl_xor_sync(0xffffffffu, sum0, 1);
        sum0 += __shfl_xor_sync(0xffffffffu, sum0, 2);
        sum1 += __shfl_xor_sync(0xffffffffu, sum1, 1);
        sum1 += __shfl_xor_sync(0xffffffffu, sum1, 2);
        l0 = l0 * sc0 + sum0;
        l1 = l1 * sc1 + sum1;
#pragma unroll
        for (int nt = 0; nt < 16; nt++) {
            o[nt][0] *= sc0; o[nt][1] *= sc0;
            o[nt][2] *= sc1; o[nt][3] *= sc1;
        }

        // ---- O += P @ V (single-pass fp16) ----
        uint32_t vB = base + A7_V + vmoff;
#pragma unroll
        for (int kk2 = 0; kk2 < 2; kk2++) {
            uint32_t aph[4];
            aph[0] = pack_h2(sacc[2 * kk2][0],     sacc[2 * kk2][1]);
            aph[1] = pack_h2(sacc[2 * kk2][2],     sacc[2 * kk2][3]);
            aph[2] = pack_h2(sacc[2 * kk2 + 1][0], sacc[2 * kk2 + 1][1]);
            aph[3] = pack_h2(sacc[2 * kk2 + 1][2], sacc[2 * kk2 + 1][3]);
#pragma unroll
            for (int ng = 0; ng < 8; ng++) {
                uint32_t rv[4];
                ldsm4(rv, vB + ng * 16 * A7_VROW + kk2 * 32);
                uint32_t b0[2] = { rv[0], rv[2] }, b1[2] = { rv[1], rv[3] };
                mma_fp16(o[2 * ng],     aph, b0);
                mma_fp16(o[2 * ng + 1], aph, b1);
            }
        }
    }

    // ---- finalize: O /= l, write fp16 hi/lo for the out-proj ----
    float inv0 = 1.f / l0, inv1 = 1.f / l1;
    int row0 = q0 + wr + g;
    size_t ob0 = (size_t)row0 * D_MODEL + h * 128 + 2 * t4;
    size_t ob1 = (size_t)(row0 + 8) * D_MODEL + h * 128 + 2 * t4;
#pragma unroll
    for (int nt = 0; nt < 16; nt++) {
        float v0 = o[nt][0] * inv0, v1 = o[nt][1] * inv0;
        float v2 = o[nt][2] * inv1, v3 = o[nt][3] * inv1;
        ushort2 hh0, ll0, hh1, ll1;
        hh0.x = f2h_bits(v0); ll0.x = f2h_bits(v0 - h_bits2f(hh0.x));
        hh0.y = f2h_bits(v1); ll0.y = f2h_bits(v1 - h_bits2f(hh0.y));
        hh1.x = f2h_bits(v2); ll1.x = f2h_bits(v2 - h_bits2f(hh1.x));
        hh1.y = f2h_bits(v3); ll1.y = f2h_bits(v3 - h_bits2f(hh1.y));
        *(ushort2*)(atthi + ob0 + nt * 8) = hh0;
        *(ushort2*)(attlo + ob0 + nt * 8) = ll0;
        *(ushort2*)(atthi + ob1 + nt * 8) = hh1;
        *(ushort2*)(attlo + ob1 + nt * 8) = ll1;
    }
}

// ---------------------------------------------------------------------------
// Launch
// ---------------------------------------------------------------------------
extern "C" void kernel_launch(void* const* d_in, const int* in_sizes, int n_in,
                              void* d_out, int out_size)
{
    const float* x    = (const float*)d_in[0];
    const float* wq   = (const float*)d_in[1];
    const float* wk   = (const float*)d_in[2];
    const float* wv   = (const float*)d_in[3];
    const float* wo   = (const float*)d_in[4];
    const float* cosp = (const float*)d_in[5];
    const float* sinp = (const float*)d_in[6];

    unsigned short *xhi, *xlo, *wqkvT, *woT;
    unsigned short *qhi, *qlo, *khi, *vthi, *atthi, *attlo;
    float *qkv;
    cudaGetSymbolAddress((void**)&xhi, g_xhi);
    cudaGetSymbolAddress((void**)&xlo, g_xlo);
    cudaGetSymbolAddress((void**)&wqkvT, g_wqkvT);
    cudaGetSymbolAddress((void**)&woT, g_woT);
    cudaGetSymbolAddress((void**)&qhi, g_qhi);
    cudaGetSymbolAddress((void**)&qlo, g_qlo);
    cudaGetSymbolAddress((void**)&khi, g_khi);
    cudaGetSymbolAddress((void**)&vthi, g_vthi);
    cudaGetSymbolAddress((void**)&atthi, g_atthi);
    cudaGetSymbolAddress((void**)&attlo, g_attlo);
    cudaGetSymbolAddress((void**)&qkv, g_qkv);

    cudaFuncSetAttribute(gemm_mma_kernel, cudaFuncAttributeMaxDynamicSharedMemorySize, G2_SMEM);
    cudaFuncSetAttribute(attn_mma_kernel, cudaFuncAttributeMaxDynamicSharedMemorySize, A7_SMEM);

    dim3 tb(32, 8);

    // 1) Split x (fp16 hi/lo)
    {
        int n4 = S_LEN * D_MODEL / 4;
        split_kernel<<<(n4 + 255) / 256, 256>>>(x, xhi, xlo, n4);
    }
    // 2-4) QKV weight transposes (single fp16)
    transpose_h_kernel<<<dim3(D_MODEL / 32, D_MODEL / 32), tb>>>(
        wq, wqkvT, D_MODEL, D_MODEL);
    transpose_h_kernel<<<dim3(1024 / 32, D_MODEL / 32), tb>>>(
        wk, wqkvT + (size_t)4096 * D_MODEL, D_MODEL, 1024);
    transpose_h_kernel<<<dim3(1024 / 32, D_MODEL / 32), tb>>>(
        wv, wqkvT + (size_t)5120 * D_MODEL, D_MODEL, 1024);

    // 5) Fused QKV projection (fp16 2-pass)
    gemm_mma_kernel<<<dim3(S_LEN / G2_BM, QKV_N / G2_BN), 256, G2_SMEM>>>(
        xhi, xlo, wqkvT, qkv, S_LEN, QKV_N, D_MODEL);

    // 6-7) RoPE + split Q (fp16 hi/lo) / K (fp16); transpose V (fp16)
    {
        int tot = S_LEN * 2560;
        rope_split_kernel<<<(tot + 255) / 256, 256>>>(qkv, cosp, sinp,
                                                      qhi, qlo, khi);
        vsplit_transpose_kernel<<<dim3(1024 / 32, S_LEN / 32), tb>>>(qkv, vthi);
    }

    // 8) wo transpose (single fp16)
    transpose_h_kernel<<<dim3(D_MODEL / 32, D_MODEL / 32), tb>>>(
        wo, woT, D_MODEL, D_MODEL);

    // 9) Tensor-core flash attention v7 (2-pass S, 1-pass PV, all fp16)
    attn_mma_kernel<<<dim3(S_LEN / 64, N_HEADS), 128, A7_SMEM>>>(
        qhi, qlo, khi, vthi, atthi, attlo);

    // 10) Output projection -> d_out (fp16 2-pass)
    gemm_mma_kernel<<<dim3(S_LEN / G2_BM, D_MODEL / G2_BN), 256, G2_SMEM>>>(
        atthi, attlo, woT, (float*)d_out, S_LEN, D_MODEL, D_MODEL);
}

// round 15
// speedup vs baseline: 1.5791x; 1.5791x over previous
#include <cuda_runtime.h>
#include <cuda_bf16.h>
#include <cuda_fp16.h>
#include <math.h>
#include <stdint.h>

// ---------------------------------------------------------------------------
// Problem constants
// ---------------------------------------------------------------------------
#define S_LEN 2048
#define D_MODEL 4096
#define N_HEADS 32
#define N_KV_HEADS 8
#define HEAD_DIM 128
#define QKV_N 6144                       // 4096 + 1024 + 1024
#define QK_SCALE 0.08838834764831845f    // 1/sqrt(128)

// ---------------------------------------------------------------------------
// Scratch (device globals; allocation is forbidden).  All fp16.
// ---------------------------------------------------------------------------
__device__ unsigned short g_xhi[S_LEN * D_MODEL];
__device__ unsigned short g_xlo[S_LEN * D_MODEL];
__device__ unsigned short g_wqkvT[QKV_N * D_MODEL];     // single fp16
__device__ unsigned short g_woT[D_MODEL * D_MODEL];     // single fp16
__device__ float g_qkv[S_LEN * QKV_N];
__device__ unsigned short g_qhi[S_LEN * D_MODEL];       // single fp16
__device__ unsigned short g_khi[S_LEN * 1024];          // single fp16
__device__ unsigned short g_vthi[1024 * S_LEN];         // [dglob][s], fp16
__device__ unsigned short g_atthi[S_LEN * D_MODEL];
__device__ unsigned short g_attlo[S_LEN * D_MODEL];

// ---------------------------------------------------------------------------
// Baseline-PTX helpers (NO tcgen05/TMA — harness compiles for compute_103)
// ---------------------------------------------------------------------------
__device__ __forceinline__ uint32_t cvta_shared(const void* p) {
    return (uint32_t)__cvta_generic_to_shared(p);
}
__device__ __forceinline__ void cp16(uint32_t dst, const void* src) {
    asm volatile("cp.async.cg.shared.global [%0], [%1], 16;" :: "r"(dst), "l"(src) : "memory");
}
__device__ __forceinline__ void cp_commit() {
    asm volatile("cp.async.commit_group;" ::: "memory");
}
template <int N> __device__ __forceinline__ void cp_wait() {
    asm volatile("cp.async.wait_group %0;" :: "n"(N) : "memory");
}
__device__ __forceinline__ void ldsm4(uint32_t* r, uint32_t addr) {
    asm volatile("ldmatrix.sync.aligned.m8n8.x4.shared.b16 {%0,%1,%2,%3}, [%4];"
                 : "=r"(r[0]), "=r"(r[1]), "=r"(r[2]), "=r"(r[3]) : "r"(addr));
}
__device__ __forceinline__ void mma_fp16(float* c, const uint32_t* a, const uint32_t* b) {
    asm volatile(
        "mma.sync.aligned.m16n8k16.row.col.f32.f16.f16.f32 "
        "{%0,%1,%2,%3}, {%4,%5,%6,%7}, {%8,%9}, {%0,%1,%2,%3};"
        : "+f"(c[0]), "+f"(c[1]), "+f"(c[2]), "+f"(c[3])
        : "r"(a[0]), "r"(a[1]), "r"(a[2]), "r"(a[3]), "r"(b[0]), "r"(b[1]));
}
__device__ __forceinline__ uint32_t pack_h2(float lo, float hi) {
    __half2 h = __floats2half2_rn(lo, hi);
    return *(uint32_t*)&h;
}
__device__ __forceinline__ unsigned short f2h_bits(float v) {
    __half h = __float2half_rn(v);
    return *(unsigned short*)&h;
}
__device__ __forceinline__ float h_bits2f(unsigned short b) {
    __half h = *(__half*)&b;
    return __half2float(h);
}

// ---------------------------------------------------------------------------
// fp32 -> fp16 hi/lo split (elementwise, vectorized)
// ---------------------------------------------------------------------------
__global__ void split_kernel(const float* __restrict__ x,
                             unsigned short* __restrict__ hi,
                             unsigned short* __restrict__ lo, int n4) {
    int i = blockIdx.x * blockDim.x + threadIdx.x;
    if (i >= n4) return;
    float4 v = ((const float4*)x)[i];
    ushort4 hh, ll;
    hh.x = f2h_bits(v.x); ll.x = f2h_bits(v.x - h_bits2f(hh.x));
    hh.y = f2h_bits(v.y); ll.y = f2h_bits(v.y - h_bits2f(hh.y));
    hh.z = f2h_bits(v.z); ll.z = f2h_bits(v.z - h_bits2f(hh.z));
    hh.w = f2h_bits(v.w); ll.w = f2h_bits(v.w - h_bits2f(hh.w));
    ((ushort4*)hi)[i] = hh;
    ((ushort4*)lo)[i] = ll;
}

// ---------------------------------------------------------------------------
// W[K x N] fp32 -> T[N x K] single fp16 (tiled transpose)
// ---------------------------------------------------------------------------
__global__ void transpose_h_kernel(const float* __restrict__ W,
                                   unsigned short* __restrict__ T,
                                   int K, int N) {
    __shared__ float t[32][33];
    int n0 = blockIdx.x * 32, k0 = blockIdx.y * 32;
    int tx = threadIdx.x, ty = threadIdx.y;  // 32 x 8
#pragma unroll
    for (int r = 0; r < 32; r += 8)
        t[ty + r][tx] = W[(size_t)(k0 + ty + r) * N + n0 + tx];
    __syncthreads();
#pragma unroll
    for (int r = 0; r < 32; r += 8) {
        size_t o = (size_t)(n0 + ty + r) * K + k0 + tx;
        T[o] = f2h_bits(t[tx][ty + r]);
    }
}

// ---------------------------------------------------------------------------
// V region of qkv -> transposed fp16 [dglob][s]
// ---------------------------------------------------------------------------
__global__ void vsplit_transpose_kernel(const float* __restrict__ qkv,
                                        unsigned short* __restrict__ Thi) {
    __shared__ float t[32][33];
    int d0 = blockIdx.x * 32, s0 = blockIdx.y * 32;
    int tx = threadIdx.x, ty = threadIdx.y;  // 32 x 8
#pragma unroll
    for (int r = 0; r < 32; r += 8)
        t[ty + r][tx] = qkv[(size_t)(s0 + ty + r) * QKV_N + 5120 + d0 + tx];
    __syncthreads();
#pragma unroll
    for (int r = 0; r < 32; r += 8) {
        size_t o = (size_t)(d0 + ty + r) * S_LEN + s0 + tx;
        Thi[o] = f2h_bits(t[tx][ty + r]);
    }
}

// ---------------------------------------------------------------------------
// RoPE + scale; Q and K both -> single fp16 now.
// ---------------------------------------------------------------------------
__global__ void rope_split_kernel(const float* __restrict__ qkv,
                                  const float* __restrict__ cosp,
                                  const float* __restrict__ sinp,
                                  unsigned short* __restrict__ qhi,
                                  unsigned short* __restrict__ khi) {
    int idx = blockIdx.x * blockDim.x + threadIdx.x;
    const int PAIRS = (D_MODEL + 1024) / 2;  // 2560 per row
    if (idx >= S_LEN * PAIRS) return;
    int s = idx / PAIRS;
    int pair = idx - s * PAIRS;
    int p = pair & 63;
    float c = cosp[s * 64 + p];
    float sn = sinp[s * 64 + p];
    bool isQ = pair < 2048;
    int col = isQ ? 2 * pair : 4096 + 2 * (pair - 2048);
    const float* src = qkv + (size_t)s * QKV_N + col;
    float t0 = src[0], t1 = src[1];
    float o0 = t0 * c - t1 * sn;
    float o1 = t0 * sn + t1 * c;
    if (isQ) {
        o0 *= QK_SCALE; o1 *= QK_SCALE;
        ushort2 hh = make_ushort2(f2h_bits(o0), f2h_bits(o1));
        *(ushort2*)(qhi + (size_t)s * D_MODEL + 2 * pair) = hh;
    } else {
        ushort2 hh = make_ushort2(f2h_bits(o0), f2h_bits(o1));
        *(ushort2*)(khi + (size_t)s * 1024 + 2 * (pair - 2048)) = hh;
    }
}

// ---------------------------------------------------------------------------
// Warp-MMA fp16 2-pass GEMM (unchanged — this is the 1417-proven config):
// C[M,N] = (Ahi+Alo)[M,K] @ B[N,K]^T, A split fp16, B single fp16.
// ---------------------------------------------------------------------------
#define G2_BM 128
#define G2_BN 128
#define G2_BK 32
#define G2_ROWB 80
#define G2_TILE 10240
#define G2_STAGE 30720       // Ahi, Alo, B
#define G2_STAGES 2
#define G2_SMEM (G2_STAGES * G2_STAGE)

__global__ __launch_bounds__(256, 2) void gemm_mma_kernel(
    const unsigned short* __restrict__ Ahi_, const unsigned short* __restrict__ Alo_,
    const unsigned short* __restrict__ B_,
    float* __restrict__ C, int M, int N, int K)
{
    extern __shared__ char smem[];
    uint32_t sb = cvta_shared(smem);
    const int tid = threadIdx.x;
    const int lane = tid & 31, wid = tid >> 5;
    const int warp_m = wid & 3;
    const int warp_n = wid >> 2;
    const int m0 = blockIdx.x * G2_BM;
    const int n0 = blockIdx.y * G2_BN;

    const unsigned short* srcs[3] = {
        Ahi_ + (size_t)m0 * K, Alo_ + (size_t)m0 * K, B_ + (size_t)n0 * K };

    auto load_stage = [&](int ch, int st) {
        uint32_t base = sb + st * G2_STAGE;
        int k0 = ch * G2_BK;
#pragma unroll
        for (int v = 0; v < 3; v++) {
            uint32_t tb = base + v * G2_TILE;
            const unsigned short* src = srcs[v];
            for (int i = tid; i < 512; i += 256) {
                int row = i >> 2, c = i & 3;
                cp16(tb + row * G2_ROWB + c * 16,
                     src + (size_t)row * K + k0 + c * 8);
            }
        }
        cp_commit();
    };

    float acc[2][8][4];
#pragma unroll
    for (int mt = 0; mt < 2; mt++)
#pragma unroll
        for (int nt = 0; nt < 8; nt++)
#pragma unroll
            for (int r = 0; r < 4; r++) acc[mt][nt][r] = 0.f;

    const int NC = K / G2_BK;
    load_stage(0, 0);

    const uint32_t a_off = (uint32_t)((lane & 15) * G2_ROWB + (lane >> 4) * 16);

    for (int ch = 0; ch < NC; ch++) {
        int st = ch & 1;
        if (ch + 1 < NC) { load_stage(ch + 1, st ^ 1); cp_wait<1>(); }
        else { cp_wait<0>(); }
        __syncthreads();

        uint32_t base = sb + st * G2_STAGE;
        uint32_t aHi = base + (warp_m * 32) * G2_ROWB + a_off;
        uint32_t aLo = aHi + G2_TILE;
        uint32_t bT = base + 2 * G2_TILE + (warp_n * 64) * G2_ROWB + a_off;

#pragma unroll
        for (int k16 = 0; k16 < 2; k16++) {
            uint32_t koff = k16 * 32;
            uint32_t ahi[2][4], alo[2][4];
#pragma unroll
            for (int mt = 0; mt < 2; mt++) {
                ldsm4(ahi[mt], aHi + mt * 16 * G2_ROWB + koff);
                ldsm4(alo[mt], aLo + mt * 16 * G2_ROWB + koff);
            }
            uint32_t bh[8][2];
#pragma unroll
            for (int ng = 0; ng < 4; ng++) {
                uint32_t r[4];
                ldsm4(r, bT + ng * 16 * G2_ROWB + koff);
                bh[2 * ng][0] = r[0]; bh[2 * ng][1] = r[2];
                bh[2 * ng + 1][0] = r[1]; bh[2 * ng + 1][1] = r[3];
            }
#pragma unroll
            for (int mt = 0; mt < 2; mt++)
#pragma unroll
                for (int nt = 0; nt < 8; nt++) {
                    mma_fp16(acc[mt][nt], ahi[mt], bh[nt]);
                    mma_fp16(acc[mt][nt], alo[mt], bh[nt]);
                }
        }
        __syncthreads();
    }

#pragma unroll
    for (int mt = 0; mt < 2; mt++) {
        int row = m0 + warp_m * 32 + mt * 16 + (lane >> 2);
#pragma unroll
        for (int nt = 0; nt < 8; nt++) {
            int col = n0 + warp_n * 64 + nt * 8 + (lane & 3) * 2;
            *(float2*)&C[(size_t)row * N + col] =
                make_float2(acc[mt][nt][0], acc[mt][nt][1]);
            *(float2*)&C[(size_t)(row + 8) * N + col] =
                make_float2(acc[mt][nt][2], acc[mt][nt][3]);
        }
    }
}

// ---------------------------------------------------------------------------
// Tensor-core flash attention v8 (causal, GQA 4:1), all fp16 MMA.
// R15: S = Q @ K^T single-pass fp16 (Q-lo pass dropped; error budget holds).
// O += P @ V single-pass fp16 (proven). 96 -> 64 MMAs per KV tile.
// 128 thr, 64 q-rows, KV=32, 2-stage; smem 55.3 KB.
// ---------------------------------------------------------------------------
#define A8_QROW 272      // 128 halfs * 2B + 16B pad
#define A8_VROW 80       // 32 halfs * 2B + 16B pad
#define A8_Q 0
#define A8_ST0 17408     // 64 * 272
#define A8_K 0
#define A8_V 8704        // 32 * 272
#define A8_STAGE_SZ 18944   // 8704 + 10240
#define A8_SMEM (A8_ST0 + 2 * A8_STAGE_SZ)   // 55296 B

__global__ __launch_bounds__(128, 2) void attn_mma_kernel(
    const unsigned short* __restrict__ Qhi,
    const unsigned short* __restrict__ Khi,
    const unsigned short* __restrict__ Vthi,
    unsigned short* __restrict__ atthi, unsigned short* __restrict__ attlo)
{
    extern __shared__ char smem[];
    uint32_t sb = cvta_shared(smem);
    const int tid = threadIdx.x;
    const int lane = tid & 31, wid = tid >> 5;          // 4 warps
    const int qblk = gridDim.x - 1 - blockIdx.x;        // heavy blocks first
    const int h = blockIdx.y;
    const int kvh = h >> 2;
    const int q0 = qblk * 64;
    const int wr = wid * 16;                            // warp rows 0..63
    const int g = lane >> 2;
    const int t4 = lane & 3;

    // ---- Q tile load (once): 64 rows x 128 halfs, single fp16 ----
    {
        const unsigned short* qsrc = Qhi + (size_t)q0 * D_MODEL + h * 128;
        for (int i = tid; i < 1024; i += 128) {
            int row = i >> 4, c = i & 15;
            cp16(sb + A8_Q + row * A8_QROW + c * 16,
                 qsrc + (size_t)row * D_MODEL + c * 8);
        }
        cp_commit();
    }

    const unsigned short* ksrc = Khi + kvh * 128;
    const unsigned short* vsrc = Vthi + (size_t)kvh * 128 * S_LEN;

    auto load_tile = [&](int j, int st) {
        uint32_t base = sb + A8_ST0 + st * A8_STAGE_SZ;
        int kv0 = j * 32;
        // K: 32 rows x 256B (fp16)
        for (int i = tid; i < 512; i += 128) {
            int row = i >> 4, c = i & 15;
            cp16(base + A8_K + row * A8_QROW + c * 16,
                 ksrc + (size_t)(kv0 + row) * 1024 + c * 8);
        }
        // V: 128 d-rows x 64B (fp16)
        for (int i = tid; i < 512; i += 128) {
            int row = i >> 2, c = i & 3;
            cp16(base + A8_V + row * A8_VROW + c * 16,
                 vsrc + (size_t)row * S_LEN + kv0 + c * 8);
        }
        cp_commit();
    };

    const int ntiles = 2 * qblk + 2;
    load_tile(0, 0);
    cp_wait<1>();          // Q group done (only tile0 outstanding)
    __syncthreads();

    // ---- hoist Q fragments into registers (16 rows x 128 K per warp) ----
    const uint32_t lmoff = (uint32_t)((lane & 15) * A8_QROW + (lane >> 4) * 16);
    uint32_t aq[8][4];
    {
        uint32_t qh = sb + A8_Q + wr * A8_QROW + lmoff;
#pragma unroll
        for (int kk = 0; kk < 8; kk++) ldsm4(aq[kk], qh + kk * 32);
    }

    float o[16][4];
#pragma unroll
    for (int nt = 0; nt < 16; nt++)
#pragma unroll
        for (int r = 0; r < 4; r++) o[nt][r] = 0.f;
    float m0 = -1e30f, m1 = -1e30f, l0 = 0.f, l1 = 0.f;

    const uint32_t vmoff = (uint32_t)((lane & 15) * A8_VROW + (lane >> 4) * 16);

    for (int j = 0; j < ntiles; j++) {
        int st = j & 1;
        __syncthreads();   // all warps done reading buffer st^1 (iter j-1)
        if (j + 1 < ntiles) { load_tile(j + 1, st ^ 1); cp_wait<1>(); }
        else { cp_wait<0>(); }
        __syncthreads();

        uint32_t base = sb + A8_ST0 + st * A8_STAGE_SZ;
        uint32_t kB = base + A8_K + lmoff;

        // ---- S = Q @ K^T (single-pass fp16), 16 rows x 32 cols / warp ----
        float sacc[4][4];
#pragma unroll
        for (int nt = 0; nt < 4; nt++)
#pragma unroll
            for (int r = 0; r < 4; r++) sacc[nt][r] = 0.f;

#pragma unroll
        for (int kk = 0; kk < 8; kk++) {
#pragma unroll
            for (int ng = 0; ng < 2; ng++) {
                uint32_t rh[4];
                ldsm4(rh, kB + ng * 16 * A8_QROW + kk * 32);
                uint32_t b0[2] = { rh[0], rh[2] }, b1[2] = { rh[1], rh[3] };
                mma_fp16(sacc[2 * ng],     aq[kk], b0);
                mma_fp16(sacc[2 * ng + 1], aq[kk], b1);
            }
        }

        // ---- causal mask (diagonal tiles only) ----
        if (j >= 2 * qblk) {
            int r0 = q0 + wr + g, r1 = r0 + 8;
            int cb = j * 32 + 2 * t4;
#pragma unroll
            for (int nt = 0; nt < 4; nt++) {
                int c0 = cb + nt * 8, c1 = c0 + 1;
                if (c0 > r0) sacc[nt][0] = -1e30f;
                if (c1 > r0) sacc[nt][1] = -1e30f;
                if (c0 > r1) sacc[nt][2] = -1e30f;
                if (c1 > r1) sacc[nt][3] = -1e30f;
            }
        }

        // ---- online softmax ----
        float mx0 = -1e30f, mx1 = -1e30f;
#pragma unroll
        for (int nt = 0; nt < 4; nt++) {
            mx0 = fmaxf(mx0, fmaxf(sacc[nt][0], sacc[nt][1]));
            mx1 = fmaxf(mx1, fmaxf(sacc[nt][2], sacc[nt][3]));
        }
        mx0 = fmaxf(mx0, __shfl_xor_sync(0xffffffffu, mx0, 1));
        mx0 = fmaxf(mx0, __shfl_xor_sync(0xffffffffu, mx0, 2));
        mx1 = fmaxf(mx1, __shfl_xor_sync(0xffffffffu, mx1, 1));
        mx1 = fmaxf(mx1, __shfl_xor_sync(0xffffffffu, mx1, 2));
        float mn0 = fmaxf(m0, mx0), mn1 = fmaxf(m1, mx1);
        float sc0 = __expf(m0 - mn0), sc1 = __expf(m1 - mn1);
        m0 = mn0; m1 = mn1;
        float sum0 = 0.f, sum1 = 0.f;
#pragma unroll
        for (int nt = 0; nt < 4; nt++) {
            sacc[nt][0] = __expf(sacc[nt][0] - mn0);
            sacc[nt][1] = __expf(sacc[nt][1] - mn0);
            sacc[nt][2] = __expf(sacc[nt][2] - mn1);
            sacc[nt][3] = __expf(sacc[nt][3] - mn1);
            sum0 += sacc[nt][0] + sacc[nt][1];
            sum1 += sacc[nt][2] + sacc[nt][3];
        }
        sum0 += __shfl_xor_sync(0xffffffffu, sum0, 1);
        sum0 += __shfl_xor_sync(0xffffffffu, sum0, 2);
        sum1 += __shfl_xor_sync(0xffffffffu, sum1, 1);
        sum1 += __shfl_xor_sync(0xffffffffu, sum1, 2);
        l0 = l0 * sc0 + sum0;
        l1 = l1 * sc1 + sum1;
#pragma unroll
        for (int nt = 0; nt < 16; nt++) {
            o[nt][0] *= sc0; o[nt][1] *= sc0;
            o[nt][2] *= sc1; o[nt][3] *= sc1;
        }

        // ---- O += P @ V (single-pass fp16) ----
        uint32_t vB = base + A8_V + vmoff;
#pragma unroll
        for (int kk2 = 0; kk2 < 2; kk2++) {
            uint32_t aph[4];
            aph[0] = pack_h2(sacc[2 * kk2][0],     sacc[2 * kk2][1]);
            aph[1] = pack_h2(sacc[2 * kk2][2],     sacc[2 * kk2][3]);
            aph[2] = pack_h2(sacc[2 * kk2 + 1][0], sacc[2 * kk2 + 1][1]);
            aph[3] = pack_h2(sacc[2 * kk2 + 1][2], sacc[2 * kk2 + 1][3]);
#pragma unroll
            for (int ng = 0; ng < 8; ng++) {
                uint32_t rv[4];
                ldsm4(rv, vB + ng * 16 * A8_VROW + kk2 * 32);
                uint32_t b0[2] = { rv[0], rv[2] }, b1[2] = { rv[1], rv[3] };
                mma_fp16(o[2 * ng],     aph, b0);
                mma_fp16(o[2 * ng + 1], aph, b1);
            }
        }
    }

    // ---- finalize: O /= l, write fp16 hi/lo for the out-proj ----
    float inv0 = 1.f / l0, inv1 = 1.f / l1;
    int row0 = q0 + wr + g;
    size_t ob0 = (size_t)row0 * D_MODEL + h * 128 + 2 * t4;
    size_t ob1 = (size_t)(row0 + 8) * D_MODEL + h * 128 + 2 * t4;
#pragma unroll
    for (int nt = 0; nt < 16; nt++) {
        float v0 = o[nt][0] * inv0, v1 = o[nt][1] * inv0;
        float v2 = o[nt][2] * inv1, v3 = o[nt][3] * inv1;
        ushort2 hh0, ll0, hh1, ll1;
        hh0.x = f2h_bits(v0); ll0.x = f2h_bits(v0 - h_bits2f(hh0.x));
        hh0.y = f2h_bits(v1); ll0.y = f2h_bits(v1 - h_bits2f(hh0.y));
        hh1.x = f2h_bits(v2); ll1.x = f2h_bits(v2 - h_bits2f(hh1.x));
        hh1.y = f2h_bits(v3); ll1.y = f2h_bits(v3 - h_bits2f(hh1.y));
        *(ushort2*)(atthi + ob0 + nt * 8) = hh0;
        *(ushort2*)(attlo + ob0 + nt * 8) = ll0;
        *(ushort2*)(atthi + ob1 + nt * 8) = hh1;
        *(ushort2*)(attlo + ob1 + nt * 8) = ll1;
    }
}

// ---------------------------------------------------------------------------
// Launch
// ---------------------------------------------------------------------------
extern "C" void kernel_launch(void* const* d_in, const int* in_sizes, int n_in,
                              void* d_out, int out_size)
{
    const float* x    = (const float*)d_in[0];
    const float* wq   = (const float*)d_in[1];
    const float* wk   = (const float*)d_in[2];
    const float* wv   = (const float*)d_in[3];
    const float* wo   = (const float*)d_in[4];
    const float* cosp = (const float*)d_in[5];
    const float* sinp = (const float*)d_in[6];

    unsigned short *xhi, *xlo, *wqkvT, *woT;
    unsigned short *qhi, *khi, *vthi, *atthi, *attlo;
    float *qkv;
    cudaGetSymbolAddress((void**)&xhi, g_xhi);
    cudaGetSymbolAddress((void**)&xlo, g_xlo);
    cudaGetSymbolAddress((void**)&wqkvT, g_wqkvT);
    cudaGetSymbolAddress((void**)&woT, g_woT);
    cudaGetSymbolAddress((void**)&qhi, g_qhi);
    cudaGetSymbolAddress((void**)&khi, g_khi);
    cudaGetSymbolAddress((void**)&vthi, g_vthi);
    cudaGetSymbolAddress((void**)&atthi, g_atthi);
    cudaGetSymbolAddress((void**)&attlo, g_attlo);
    cudaGetSymbolAddress((void**)&qkv, g_qkv);

    cudaFuncSetAttribute(gemm_mma_kernel, cudaFuncAttributeMaxDynamicSharedMemorySize, G2_SMEM);
    cudaFuncSetAttribute(attn_mma_kernel, cudaFuncAttributeMaxDynamicSharedMemorySize, A8_SMEM);

    dim3 tb(32, 8);

    // 1) Split x (fp16 hi/lo)
    {
        int n4 = S_LEN * D_MODEL / 4;
        split_kernel<<<(n4 + 255) / 256, 256>>>(x, xhi, xlo, n4);
    }
    // 2-4) QKV weight transposes (single fp16)
    transpose_h_kernel<<<dim3(D_MODEL / 32, D_MODEL / 32), tb>>>(
        wq, wqkvT, D_MODEL, D_MODEL);
    transpose_h_kernel<<<dim3(1024 / 32, D_MODEL / 32), tb>>>(
        wk, wqkvT + (size_t)4096 * D_MODEL, D_MODEL, 1024);
    transpose_h_kernel<<<dim3(1024 / 32, D_MODEL / 32), tb>>>(
        wv, wqkvT + (size_t)5120 * D_MODEL, D_MODEL, 1024);

    // 5) Fused QKV projection (fp16 2-pass)
    gemm_mma_kernel<<<dim3(S_LEN / G2_BM, QKV_N / G2_BN), 256, G2_SMEM>>>(
        xhi, xlo, wqkvT, qkv, S_LEN, QKV_N, D_MODEL);

    // 6-7) RoPE (Q,K single fp16); transpose V (fp16)
    {
        int tot = S_LEN * 2560;
        rope_split_kernel<<<(tot + 255) / 256, 256>>>(qkv, cosp, sinp, qhi, khi);
        vsplit_transpose_kernel<<<dim3(1024 / 32, S_LEN / 32), tb>>>(qkv, vthi);
    }

    // 8) wo transpose (single fp16)
    transpose_h_kernel<<<dim3(D_MODEL / 32, D_MODEL / 32), tb>>>(
        wo, woT, D_MODEL, D_MODEL);

    // 9) Tensor-core flash attention v8 (1-pass S, 1-pass PV)
    attn_mma_kernel<<<dim3(S_LEN / 64, N_HEADS), 128, A8_SMEM>>>(
        qhi, khi, vthi, atthi, attlo);

    // 10) Output projection -> d_out (fp16 2-pass)
    gemm_mma_kernel<<<dim3(S_LEN / G2_BM, D_MODEL / G2_BN), 256, G2_SMEM>>>(
        atthi, attlo, woT, (float*)d_out, S_LEN, D_MODEL, D_MODEL);
}

// round 16
// speedup vs baseline: 1.8569x; 1.1759x over previous
#include <cuda_runtime.h>
#include <cuda_bf16.h>
#include <cuda_fp16.h>
#include <math.h>
#include <stdint.h>

// ---------------------------------------------------------------------------
// Problem constants
// ---------------------------------------------------------------------------
#define S_LEN 2048
#define D_MODEL 4096
#define N_HEADS 32
#define N_KV_HEADS 8
#define HEAD_DIM 128
#define QKV_N 6144                       // 4096 + 1024 + 1024
#define QK_SCALE 0.08838834764831845f    // 1/sqrt(128)

// ---------------------------------------------------------------------------
// Scratch (device globals; allocation is forbidden).  All fp16.
// ---------------------------------------------------------------------------
__device__ unsigned short g_xhi[S_LEN * D_MODEL];
__device__ unsigned short g_xlo[S_LEN * D_MODEL];
__device__ unsigned short g_wqkvT[QKV_N * D_MODEL];     // single fp16
__device__ unsigned short g_woT[D_MODEL * D_MODEL];     // single fp16
__device__ float g_qkv[S_LEN * QKV_N];
__device__ unsigned short g_qhi[S_LEN * D_MODEL];       // single fp16
__device__ unsigned short g_khi[S_LEN * 1024];          // single fp16
__device__ unsigned short g_vthi[1024 * S_LEN];         // [dglob][s], fp16
__device__ unsigned short g_atthi[S_LEN * D_MODEL];     // single fp16

// ---------------------------------------------------------------------------
// Baseline-PTX helpers (NO tcgen05/TMA — harness compiles for compute_103)
// ---------------------------------------------------------------------------
__device__ __forceinline__ uint32_t cvta_shared(const void* p) {
    return (uint32_t)__cvta_generic_to_shared(p);
}
__device__ __forceinline__ void cp16(uint32_t dst, const void* src) {
    asm volatile("cp.async.cg.shared.global [%0], [%1], 16;" :: "r"(dst), "l"(src) : "memory");
}
__device__ __forceinline__ void cp_commit() {
    asm volatile("cp.async.commit_group;" ::: "memory");
}
template <int N> __device__ __forceinline__ void cp_wait() {
    asm volatile("cp.async.wait_group %0;" :: "n"(N) : "memory");
}
__device__ __forceinline__ void ldsm4(uint32_t* r, uint32_t addr) {
    asm volatile("ldmatrix.sync.aligned.m8n8.x4.shared.b16 {%0,%1,%2,%3}, [%4];"
                 : "=r"(r[0]), "=r"(r[1]), "=r"(r[2]), "=r"(r[3]) : "r"(addr));
}
__device__ __forceinline__ void mma_fp16(float* c, const uint32_t* a, const uint32_t* b) {
    asm volatile(
        "mma.sync.aligned.m16n8k16.row.col.f32.f16.f16.f32 "
        "{%0,%1,%2,%3}, {%4,%5,%6,%7}, {%8,%9}, {%0,%1,%2,%3};"
        : "+f"(c[0]), "+f"(c[1]), "+f"(c[2]), "+f"(c[3])
        : "r"(a[0]), "r"(a[1]), "r"(a[2]), "r"(a[3]), "r"(b[0]), "r"(b[1]));
}
__device__ __forceinline__ uint32_t pack_h2(float lo, float hi) {
    __half2 h = __floats2half2_rn(lo, hi);
    return *(uint32_t*)&h;
}
__device__ __forceinline__ unsigned short f2h_bits(float v) {
    __half h = __float2half_rn(v);
    return *(unsigned short*)&h;
}
__device__ __forceinline__ float h_bits2f(unsigned short b) {
    __half h = *(__half*)&b;
    return __half2float(h);
}

// ---------------------------------------------------------------------------
// fp32 -> fp16 hi/lo split (elementwise, vectorized)
// ---------------------------------------------------------------------------
__global__ void split_kernel(const float* __restrict__ x,
                             unsigned short* __restrict__ hi,
                             unsigned short* __restrict__ lo, int n4) {
    int i = blockIdx.x * blockDim.x + threadIdx.x;
    if (i >= n4) return;
    float4 v = ((const float4*)x)[i];
    ushort4 hh, ll;
    hh.x = f2h_bits(v.x); ll.x = f2h_bits(v.x - h_bits2f(hh.x));
    hh.y = f2h_bits(v.y); ll.y = f2h_bits(v.y - h_bits2f(hh.y));
    hh.z = f2h_bits(v.z); ll.z = f2h_bits(v.z - h_bits2f(hh.z));
    hh.w = f2h_bits(v.w); ll.w = f2h_bits(v.w - h_bits2f(hh.w));
    ((ushort4*)hi)[i] = hh;
    ((ushort4*)lo)[i] = ll;
}

// ---------------------------------------------------------------------------
// W[K x N] fp32 -> T[N x K] single fp16 (tiled transpose)
// ---------------------------------------------------------------------------
__global__ void transpose_h_kernel(const float* __restrict__ W,
                                   unsigned short* __restrict__ T,
                                   int K, int N) {
    __shared__ float t[32][33];
    int n0 = blockIdx.x * 32, k0 = blockIdx.y * 32;
    int tx = threadIdx.x, ty = threadIdx.y;  // 32 x 8
#pragma unroll
    for (int r = 0; r < 32; r += 8)
        t[ty + r][tx] = W[(size_t)(k0 + ty + r) * N + n0 + tx];
    __syncthreads();
#pragma unroll
    for (int r = 0; r < 32; r += 8) {
        size_t o = (size_t)(n0 + ty + r) * K + k0 + tx;
        T[o] = f2h_bits(t[tx][ty + r]);
    }
}

// ---------------------------------------------------------------------------
// V region of qkv -> transposed fp16 [dglob][s]
// ---------------------------------------------------------------------------
__global__ void vsplit_transpose_kernel(const float* __restrict__ qkv,
                                        unsigned short* __restrict__ Thi) {
    __shared__ float t[32][33];
    int d0 = blockIdx.x * 32, s0 = blockIdx.y * 32;
    int tx = threadIdx.x, ty = threadIdx.y;  // 32 x 8
#pragma unroll
    for (int r = 0; r < 32; r += 8)
        t[ty + r][tx] = qkv[(size_t)(s0 + ty + r) * QKV_N + 5120 + d0 + tx];
    __syncthreads();
#pragma unroll
    for (int r = 0; r < 32; r += 8) {
        size_t o = (size_t)(d0 + ty + r) * S_LEN + s0 + tx;
        Thi[o] = f2h_bits(t[tx][ty + r]);
    }
}

// ---------------------------------------------------------------------------
// RoPE + scale; Q and K both -> single fp16.
// ---------------------------------------------------------------------------
__global__ void rope_split_kernel(const float* __restrict__ qkv,
                                  const float* __restrict__ cosp,
                                  const float* __restrict__ sinp,
                                  unsigned short* __restrict__ qhi,
                                  unsigned short* __restrict__ khi) {
    int idx = blockIdx.x * blockDim.x + threadIdx.x;
    const int PAIRS = (D_MODEL + 1024) / 2;  // 2560 per row
    if (idx >= S_LEN * PAIRS) return;
    int s = idx / PAIRS;
    int pair = idx - s * PAIRS;
    int p = pair & 63;
    float c = cosp[s * 64 + p];
    float sn = sinp[s * 64 + p];
    bool isQ = pair < 2048;
    int col = isQ ? 2 * pair : 4096 + 2 * (pair - 2048);
    const float* src = qkv + (size_t)s * QKV_N + col;
    float t0 = src[0], t1 = src[1];
    float o0 = t0 * c - t1 * sn;
    float o1 = t0 * sn + t1 * c;
    if (isQ) {
        o0 *= QK_SCALE; o1 *= QK_SCALE;
        ushort2 hh = make_ushort2(f2h_bits(o0), f2h_bits(o1));
        *(ushort2*)(qhi + (size_t)s * D_MODEL + 2 * pair) = hh;
    } else {
        ushort2 hh = make_ushort2(f2h_bits(o0), f2h_bits(o1));
        *(ushort2*)(khi + (size_t)s * 1024 + 2 * (pair - 2048)) = hh;
    }
}

// ---------------------------------------------------------------------------
// Warp-MMA fp16 2-pass GEMM (QKV projection; 1378-proven config):
// C[M,N] = (Ahi+Alo)[M,K] @ B[N,K]^T, A split fp16, B single fp16.
// ---------------------------------------------------------------------------
#define G2_BM 128
#define G2_BN 128
#define G2_BK 32
#define G2_ROWB 80
#define G2_TILE 10240
#define G2_STAGE 30720       // Ahi, Alo, B
#define G2_STAGES 2
#define G2_SMEM (G2_STAGES * G2_STAGE)

__global__ __launch_bounds__(256, 2) void gemm_mma_kernel(
    const unsigned short* __restrict__ Ahi_, const unsigned short* __restrict__ Alo_,
    const unsigned short* __restrict__ B_,
    float* __restrict__ C, int M, int N, int K)
{
    extern __shared__ char smem[];
    uint32_t sb = cvta_shared(smem);
    const int tid = threadIdx.x;
    const int lane = tid & 31, wid = tid >> 5;
    const int warp_m = wid & 3;
    const int warp_n = wid >> 2;
    const int m0 = blockIdx.x * G2_BM;
    const int n0 = blockIdx.y * G2_BN;

    const unsigned short* srcs[3] = {
        Ahi_ + (size_t)m0 * K, Alo_ + (size_t)m0 * K, B_ + (size_t)n0 * K };

    auto load_stage = [&](int ch, int st) {
        uint32_t base = sb + st * G2_STAGE;
        int k0 = ch * G2_BK;
#pragma unroll
        for (int v = 0; v < 3; v++) {
            uint32_t tb = base + v * G2_TILE;
            const unsigned short* src = srcs[v];
            for (int i = tid; i < 512; i += 256) {
                int row = i >> 2, c = i & 3;
                cp16(tb + row * G2_ROWB + c * 16,
                     src + (size_t)row * K + k0 + c * 8);
            }
        }
        cp_commit();
    };

    float acc[2][8][4];
#pragma unroll
    for (int mt = 0; mt < 2; mt++)
#pragma unroll
        for (int nt = 0; nt < 8; nt++)
#pragma unroll
            for (int r = 0; r < 4; r++) acc[mt][nt][r] = 0.f;

    const int NC = K / G2_BK;
    load_stage(0, 0);

    const uint32_t a_off = (uint32_t)((lane & 15) * G2_ROWB + (lane >> 4) * 16);

    for (int ch = 0; ch < NC; ch++) {
        int st = ch & 1;
        if (ch + 1 < NC) { load_stage(ch + 1, st ^ 1); cp_wait<1>(); }
        else { cp_wait<0>(); }
        __syncthreads();

        uint32_t base = sb + st * G2_STAGE;
        uint32_t aHi = base + (warp_m * 32) * G2_ROWB + a_off;
        uint32_t aLo = aHi + G2_TILE;
        uint32_t bT = base + 2 * G2_TILE + (warp_n * 64) * G2_ROWB + a_off;

#pragma unroll
        for (int k16 = 0; k16 < 2; k16++) {
            uint32_t koff = k16 * 32;
            uint32_t ahi[2][4], alo[2][4];
#pragma unroll
            for (int mt = 0; mt < 2; mt++) {
                ldsm4(ahi[mt], aHi + mt * 16 * G2_ROWB + koff);
                ldsm4(alo[mt], aLo + mt * 16 * G2_ROWB + koff);
            }
            uint32_t bh[8][2];
#pragma unroll
            for (int ng = 0; ng < 4; ng++) {
                uint32_t r[4];
                ldsm4(r, bT + ng * 16 * G2_ROWB + koff);
                bh[2 * ng][0] = r[0]; bh[2 * ng][1] = r[2];
                bh[2 * ng + 1][0] = r[1]; bh[2 * ng + 1][1] = r[3];
            }
#pragma unroll
            for (int mt = 0; mt < 2; mt++)
#pragma unroll
                for (int nt = 0; nt < 8; nt++) {
                    mma_fp16(acc[mt][nt], ahi[mt], bh[nt]);
                    mma_fp16(acc[mt][nt], alo[mt], bh[nt]);
                }
        }
        __syncthreads();
    }

#pragma unroll
    for (int mt = 0; mt < 2; mt++) {
        int row = m0 + warp_m * 32 + mt * 16 + (lane >> 2);
#pragma unroll
        for (int nt = 0; nt < 8; nt++) {
            int col = n0 + warp_n * 64 + nt * 8 + (lane & 3) * 2;
            *(float2*)&C[(size_t)row * N + col] =
                make_float2(acc[mt][nt][0], acc[mt][nt][1]);
            *(float2*)&C[(size_t)(row + 8) * N + col] =
                make_float2(acc[mt][nt][2], acc[mt][nt][3]);
        }
    }
}

// ---------------------------------------------------------------------------
// Warp-MMA fp16 1-pass GEMM (output projection): C = A @ B^T, both single fp16.
// ---------------------------------------------------------------------------
#define G1_STAGE 20480       // A, B
#define G1_SMEM (2 * G1_STAGE)

__global__ __launch_bounds__(256, 2) void gemm1_mma_kernel(
    const unsigned short* __restrict__ A_, const unsigned short* __restrict__ B_,
    float* __restrict__ C, int M, int N, int K)
{
    extern __shared__ char smem[];
    uint32_t sb = cvta_shared(smem);
    const int tid = threadIdx.x;
    const int lane = tid & 31, wid = tid >> 5;
    const int warp_m = wid & 3;
    const int warp_n = wid >> 2;
    const int m0 = blockIdx.x * G2_BM;
    const int n0 = blockIdx.y * G2_BN;

    const unsigned short* srcs[2] = { A_ + (size_t)m0 * K, B_ + (size_t)n0 * K };

    auto load_stage = [&](int ch, int st) {
        uint32_t base = sb + st * G1_STAGE;
        int k0 = ch * G2_BK;
#pragma unroll
        for (int v = 0; v < 2; v++) {
            uint32_t tb = base + v * G2_TILE;
            const unsigned short* src = srcs[v];
            for (int i = tid; i < 512; i += 256) {
                int row = i >> 2, c = i & 3;
                cp16(tb + row * G2_ROWB + c * 16,
                     src + (size_t)row * K + k0 + c * 8);
            }
        }
        cp_commit();
    };

    float acc[2][8][4];
#pragma unroll
    for (int mt = 0; mt < 2; mt++)
#pragma unroll
        for (int nt = 0; nt < 8; nt++)
#pragma unroll
            for (int r = 0; r < 4; r++) acc[mt][nt][r] = 0.f;

    const int NC = K / G2_BK;
    load_stage(0, 0);

    const uint32_t a_off = (uint32_t)((lane & 15) * G2_ROWB + (lane >> 4) * 16);

    for (int ch = 0; ch < NC; ch++) {
        int st = ch & 1;
        if (ch + 1 < NC) { load_stage(ch + 1, st ^ 1); cp_wait<1>(); }
        else { cp_wait<0>(); }
        __syncthreads();

        uint32_t base = sb + st * G1_STAGE;
        uint32_t aT = base + (warp_m * 32) * G2_ROWB + a_off;
        uint32_t bT = base + G2_TILE + (warp_n * 64) * G2_ROWB + a_off;

#pragma unroll
        for (int k16 = 0; k16 < 2; k16++) {
            uint32_t koff = k16 * 32;
            uint32_t am[2][4];
#pragma unroll
            for (int mt = 0; mt < 2; mt++)
                ldsm4(am[mt], aT + mt * 16 * G2_ROWB + koff);
            uint32_t bh[8][2];
#pragma unroll
            for (int ng = 0; ng < 4; ng++) {
                uint32_t r[4];
                ldsm4(r, bT + ng * 16 * G2_ROWB + koff);
                bh[2 * ng][0] = r[0]; bh[2 * ng][1] = r[2];
                bh[2 * ng + 1][0] = r[1]; bh[2 * ng + 1][1] = r[3];
            }
#pragma unroll
            for (int mt = 0; mt < 2; mt++)
#pragma unroll
                for (int nt = 0; nt < 8; nt++)
                    mma_fp16(acc[mt][nt], am[mt], bh[nt]);
        }
        __syncthreads();
    }

#pragma unroll
    for (int mt = 0; mt < 2; mt++) {
        int row = m0 + warp_m * 32 + mt * 16 + (lane >> 2);
#pragma unroll
        for (int nt = 0; nt < 8; nt++) {
            int col = n0 + warp_n * 64 + nt * 8 + (lane & 3) * 2;
            *(float2*)&C[(size_t)row * N + col] =
                make_float2(acc[mt][nt][0], acc[mt][nt][1]);
            *(float2*)&C[(size_t)(row + 8) * N + col] =
                make_float2(acc[mt][nt][2], acc[mt][nt][3]);
        }
    }
}

// ---------------------------------------------------------------------------
// Tensor-core flash attention v9 (causal, GQA 4:1), all fp16 1-pass MMA.
// R16: KV tile 32 -> 64 (halves per-tile softmax/barrier overhead).
// 128 thr, 64 q-rows, 2-stage; smem 89088 B -> 2 CTAs/SM.
// Output: single fp16 (att-lo dropped; out-proj is 1-pass).
// ---------------------------------------------------------------------------
#define A9_QROW 272      // 128 halfs * 2B + 16B pad
#define A9_VROW 144      // 64 halfs * 2B + 16B pad
#define A9_Q 0
#define A9_ST0 17408     // 64 * 272
#define A9_K 0
#define A9_V 17408       // 64 rows * 272
#define A9_STAGE_SZ 35840   // 17408 + 128*144
#define A9_SMEM (A9_ST0 + 2 * A9_STAGE_SZ)   // 89088 B -> 2 CTAs/SM

__global__ __launch_bounds__(128, 2) void attn_mma_kernel(
    const unsigned short* __restrict__ Qhi,
    const unsigned short* __restrict__ Khi,
    const unsigned short* __restrict__ Vthi,
    unsigned short* __restrict__ atthi)
{
    extern __shared__ char smem[];
    uint32_t sb = cvta_shared(smem);
    const int tid = threadIdx.x;
    const int lane = tid & 31, wid = tid >> 5;          // 4 warps
    const int qblk = gridDim.x - 1 - blockIdx.x;        // heavy blocks first
    const int h = blockIdx.y;
    const int kvh = h >> 2;
    const int q0 = qblk * 64;
    const int wr = wid * 16;                            // warp rows 0..63
    const int g = lane >> 2;
    const int t4 = lane & 3;

    // ---- Q tile load (once): 64 rows x 128 halfs, single fp16 ----
    {
        const unsigned short* qsrc = Qhi + (size_t)q0 * D_MODEL + h * 128;
        for (int i = tid; i < 1024; i += 128) {
            int row = i >> 4, c = i & 15;
            cp16(sb + A9_Q + row * A9_QROW + c * 16,
                 qsrc + (size_t)row * D_MODEL + c * 8);
        }
        cp_commit();
    }

    const unsigned short* ksrc = Khi + kvh * 128;
    const unsigned short* vsrc = Vthi + (size_t)kvh * 128 * S_LEN;

    auto load_tile = [&](int j, int st) {
        uint32_t base = sb + A9_ST0 + st * A9_STAGE_SZ;
        int kv0 = j * 64;
        // K: 64 rows x 256B (fp16)
        for (int i = tid; i < 1024; i += 128) {
            int row = i >> 4, c = i & 15;
            cp16(base + A9_K + row * A9_QROW + c * 16,
                 ksrc + (size_t)(kv0 + row) * 1024 + c * 8);
        }
        // V: 128 d-rows x 128B (fp16, 64 kv cols)
        for (int i = tid; i < 1024; i += 128) {
            int row = i >> 3, c = i & 7;
            cp16(base + A9_V + row * A9_VROW + c * 16,
                 vsrc + (size_t)row * S_LEN + kv0 + c * 8);
        }
        cp_commit();
    };

    const int ntiles = qblk + 1;
    load_tile(0, 0);
    cp_wait<1>();          // Q group done (only tile0 outstanding)
    __syncthreads();

    // ---- hoist Q fragments into registers (16 rows x 128 K per warp) ----
    const uint32_t lmoff = (uint32_t)((lane & 15) * A9_QROW + (lane >> 4) * 16);
    uint32_t aq[8][4];
    {
        uint32_t qh = sb + A9_Q + wr * A9_QROW + lmoff;
#pragma unroll
        for (int kk = 0; kk < 8; kk++) ldsm4(aq[kk], qh + kk * 32);
    }

    float o[16][4];
#pragma unroll
    for (int nt = 0; nt < 16; nt++)
#pragma unroll
        for (int r = 0; r < 4; r++) o[nt][r] = 0.f;
    float m0 = -1e30f, m1 = -1e30f, l0 = 0.f, l1 = 0.f;

    const uint32_t vmoff = (uint32_t)((lane & 15) * A9_VROW + (lane >> 4) * 16);

    for (int j = 0; j < ntiles; j++) {
        int st = j & 1;
        __syncthreads();   // all warps done reading buffer st^1 (iter j-1)
        if (j + 1 < ntiles) { load_tile(j + 1, st ^ 1); cp_wait<1>(); }
        else { cp_wait<0>(); }
        __syncthreads();

        uint32_t base = sb + A9_ST0 + st * A9_STAGE_SZ;
        uint32_t kB = base + A9_K + lmoff;

        // ---- S = Q @ K^T (single-pass fp16), 16 rows x 64 cols / warp ----
        float sacc[8][4];
#pragma unroll
        for (int nt = 0; nt < 8; nt++)
#pragma unroll
            for (int r = 0; r < 4; r++) sacc[nt][r] = 0.f;

#pragma unroll
        for (int kk = 0; kk < 8; kk++) {
#pragma unroll
            for (int ng = 0; ng < 4; ng++) {
                uint32_t rh[4];
                ldsm4(rh, kB + ng * 16 * A9_QROW + kk * 32);
                uint32_t b0[2] = { rh[0], rh[2] }, b1[2] = { rh[1], rh[3] };
                mma_fp16(sacc[2 * ng],     aq[kk], b0);
                mma_fp16(sacc[2 * ng + 1], aq[kk], b1);
            }
        }

        // ---- causal mask (diagonal tile only: j == qblk) ----
        if (j == qblk) {
            int r0 = q0 + wr + g, r1 = r0 + 8;
            int cb = j * 64 + 2 * t4;
#pragma unroll
            for (int nt = 0; nt < 8; nt++) {
                int c0 = cb + nt * 8, c1 = c0 + 1;
                if (c0 > r0) sacc[nt][0] = -1e30f;
                if (c1 > r0) sacc[nt][1] = -1e30f;
                if (c0 > r1) sacc[nt][2] = -1e30f;
                if (c1 > r1) sacc[nt][3] = -1e30f;
            }
        }

        // ---- online softmax (once per 64 kv) ----
        float mx0 = -1e30f, mx1 = -1e30f;
#pragma unroll
        for (int nt = 0; nt < 8; nt++) {
            mx0 = fmaxf(mx0, fmaxf(sacc[nt][0], sacc[nt][1]));
            mx1 = fmaxf(mx1, fmaxf(sacc[nt][2], sacc[nt][3]));
        }
        mx0 = fmaxf(mx0, __shfl_xor_sync(0xffffffffu, mx0, 1));
        mx0 = fmaxf(mx0, __shfl_xor_sync(0xffffffffu, mx0, 2));
        mx1 = fmaxf(mx1, __shfl_xor_sync(0xffffffffu, mx1, 1));
        mx1 = fmaxf(mx1, __shfl_xor_sync(0xffffffffu, mx1, 2));
        float mn0 = fmaxf(m0, mx0), mn1 = fmaxf(m1, mx1);
        float sc0 = __expf(m0 - mn0), sc1 = __expf(m1 - mn1);
        m0 = mn0; m1 = mn1;
        float sum0 = 0.f, sum1 = 0.f;
#pragma unroll
        for (int nt = 0; nt < 8; nt++) {
            sacc[nt][0] = __expf(sacc[nt][0] - mn0);
            sacc[nt][1] = __expf(sacc[nt][1] - mn0);
            sacc[nt][2] = __expf(sacc[nt][2] - mn1);
            sacc[nt][3] = __expf(sacc[nt][3] - mn1);
            sum0 += sacc[nt][0] + sacc[nt][1];
            sum1 += sacc[nt][2] + sacc[nt][3];
        }
        sum0 += __shfl_xor_sync(0xffffffffu, sum0, 1);
        sum0 += __shfl_xor_sync(0xffffffffu, sum0, 2);
        sum1 += __shfl_xor_sync(0xffffffffu, sum1, 1);
        sum1 += __shfl_xor_sync(0xffffffffu, sum1, 2);
        l0 = l0 * sc0 + sum0;
        l1 = l1 * sc1 + sum1;
#pragma unroll
        for (int nt = 0; nt < 16; nt++) {
            o[nt][0] *= sc0; o[nt][1] *= sc0;
            o[nt][2] *= sc1; o[nt][3] *= sc1;
        }

        // ---- O += P @ V (single-pass fp16), K-dim = 64 ----
        uint32_t vB = base + A9_V + vmoff;
#pragma unroll
        for (int kk2 = 0; kk2 < 4; kk2++) {
            uint32_t aph[4];
            aph[0] = pack_h2(sacc[2 * kk2][0],     sacc[2 * kk2][1]);
            aph[1] = pack_h2(sacc[2 * kk2][2],     sacc[2 * kk2][3]);
            aph[2] = pack_h2(sacc[2 * kk2 + 1][0], sacc[2 * kk2 + 1][1]);
            aph[3] = pack_h2(sacc[2 * kk2 + 1][2], sacc[2 * kk2 + 1][3]);
#pragma unroll
            for (int ng = 0; ng < 8; ng++) {
                uint32_t rv[4];
                ldsm4(rv, vB + ng * 16 * A9_VROW + kk2 * 32);
                uint32_t b0[2] = { rv[0], rv[2] }, b1[2] = { rv[1], rv[3] };
                mma_fp16(o[2 * ng],     aph, b0);
                mma_fp16(o[2 * ng + 1], aph, b1);
            }
        }
    }

    // ---- finalize: O /= l, write single fp16 ----
    float inv0 = 1.f / l0, inv1 = 1.f / l1;
    int row0 = q0 + wr + g;
    size_t ob0 = (size_t)row0 * D_MODEL + h * 128 + 2 * t4;
    size_t ob1 = (size_t)(row0 + 8) * D_MODEL + h * 128 + 2 * t4;
#pragma unroll
    for (int nt = 0; nt < 16; nt++) {
        ushort2 hh0 = make_ushort2(f2h_bits(o[nt][0] * inv0), f2h_bits(o[nt][1] * inv0));
        ushort2 hh1 = make_ushort2(f2h_bits(o[nt][2] * inv1), f2h_bits(o[nt][3] * inv1));
        *(ushort2*)(atthi + ob0 + nt * 8) = hh0;
        *(ushort2*)(atthi + ob1 + nt * 8) = hh1;
    }
}

// ---------------------------------------------------------------------------
// Launch
// ---------------------------------------------------------------------------
extern "C" void kernel_launch(void* const* d_in, const int* in_sizes, int n_in,
                              void* d_out, int out_size)
{
    const float* x    = (const float*)d_in[0];
    const float* wq   = (const float*)d_in[1];
    const float* wk   = (const float*)d_in[2];
    const float* wv   = (const float*)d_in[3];
    const float* wo   = (const float*)d_in[4];
    const float* cosp = (const float*)d_in[5];
    const float* sinp = (const float*)d_in[6];

    unsigned short *xhi, *xlo, *wqkvT, *woT;
    unsigned short *qhi, *khi, *vthi, *atthi;
    float *qkv;
    cudaGetSymbolAddress((void**)&xhi, g_xhi);
    cudaGetSymbolAddress((void**)&xlo, g_xlo);
    cudaGetSymbolAddress((void**)&wqkvT, g_wqkvT);
    cudaGetSymbolAddress((void**)&woT, g_woT);
    cudaGetSymbolAddress((void**)&qhi, g_qhi);
    cudaGetSymbolAddress((void**)&khi, g_khi);
    cudaGetSymbolAddress((void**)&vthi, g_vthi);
    cudaGetSymbolAddress((void**)&atthi, g_atthi);
    cudaGetSymbolAddress((void**)&qkv, g_qkv);

    cudaFuncSetAttribute(gemm_mma_kernel, cudaFuncAttributeMaxDynamicSharedMemorySize, G2_SMEM);
    cudaFuncSetAttribute(gemm1_mma_kernel, cudaFuncAttributeMaxDynamicSharedMemorySize, G1_SMEM);
    cudaFuncSetAttribute(attn_mma_kernel, cudaFuncAttributeMaxDynamicSharedMemorySize, A9_SMEM);

    dim3 tb(32, 8);

    // 1) Split x (fp16 hi/lo)
    {
        int n4 = S_LEN * D_MODEL / 4;
        split_kernel<<<(n4 + 255) / 256, 256>>>(x, xhi, xlo, n4);
    }
    // 2-4) QKV weight transposes (single fp16)
    transpose_h_kernel<<<dim3(D_MODEL / 32, D_MODEL / 32), tb>>>(
        wq, wqkvT, D_MODEL, D_MODEL);
    transpose_h_kernel<<<dim3(1024 / 32, D_MODEL / 32), tb>>>(
        wk, wqkvT + (size_t)4096 * D_MODEL, D_MODEL, 1024);
    transpose_h_kernel<<<dim3(1024 / 32, D_MODEL / 32), tb>>>(
        wv, wqkvT + (size_t)5120 * D_MODEL, D_MODEL, 1024);

    // 5) Fused QKV projection (fp16 2-pass — precision anchor)
    gemm_mma_kernel<<<dim3(S_LEN / G2_BM, QKV_N / G2_BN), 256, G2_SMEM>>>(
        xhi, xlo, wqkvT, qkv, S_LEN, QKV_N, D_MODEL);

    // 6-7) RoPE (Q,K single fp16); transpose V (fp16)
    {
        int tot = S_LEN * 2560;
        rope_split_kernel<<<(tot + 255) / 256, 256>>>(qkv, cosp, sinp, qhi, khi);
        vsplit_transpose_kernel<<<dim3(1024 / 32, S_LEN / 32), tb>>>(qkv, vthi);
    }

    // 8) wo transpose (single fp16)
    transpose_h_kernel<<<dim3(D_MODEL / 32, D_MODEL / 32), tb>>>(
        wo, woT, D_MODEL, D_MODEL);

    // 9) Tensor-core flash attention v9 (KV=64, fp16 out)
    attn_mma_kernel<<<dim3(S_LEN / 64, N_HEADS), 128, A9_SMEM>>>(
        qhi, khi, vthi, atthi);

    // 10) Output projection -> d_out (fp16 1-pass)
    gemm1_mma_kernel<<<dim3(S_LEN / G2_BM, D_MODEL / G2_BN), 256, G1_SMEM>>>(
        atthi, woT, (float*)d_out, S_LEN, D_MODEL, D_MODEL);
}

// round 17
// speedup vs baseline: 2.4428x; 1.3156x over previous
#include <cuda_runtime.h>
#include <cuda_bf16.h>
#include <cuda_fp16.h>
#include <math.h>
#include <stdint.h>

// ---------------------------------------------------------------------------
// Problem constants
// ---------------------------------------------------------------------------
#define S_LEN 2048
#define D_MODEL 4096
#define N_HEADS 32
#define N_KV_HEADS 8
#define HEAD_DIM 128
#define QKV_N 6144                       // 4096 + 1024 + 1024
#define QK_SCALE 0.08838834764831845f    // 1/sqrt(128)

// ---------------------------------------------------------------------------
// Scratch (device globals; allocation is forbidden).  All fp16, all 1-pass.
// ---------------------------------------------------------------------------
__device__ unsigned short g_xh[S_LEN * D_MODEL];        // single fp16
__device__ unsigned short g_wqkvT[QKV_N * D_MODEL];     // single fp16
__device__ unsigned short g_woT[D_MODEL * D_MODEL];     // single fp16
__device__ float g_qkv[S_LEN * QKV_N];
__device__ unsigned short g_qhi[S_LEN * D_MODEL];       // single fp16
__device__ unsigned short g_khi[S_LEN * 1024];          // single fp16
__device__ unsigned short g_vthi[1024 * S_LEN];         // [dglob][s], fp16
__device__ unsigned short g_atthi[S_LEN * D_MODEL];     // single fp16

// ---------------------------------------------------------------------------
// Baseline-PTX helpers (NO tcgen05/TMA — harness compiles for compute_103)
// ---------------------------------------------------------------------------
__device__ __forceinline__ uint32_t cvta_shared(const void* p) {
    return (uint32_t)__cvta_generic_to_shared(p);
}
__device__ __forceinline__ void cp16(uint32_t dst, const void* src) {
    asm volatile("cp.async.cg.shared.global [%0], [%1], 16;" :: "r"(dst), "l"(src) : "memory");
}
__device__ __forceinline__ void cp_commit() {
    asm volatile("cp.async.commit_group;" ::: "memory");
}
template <int N> __device__ __forceinline__ void cp_wait() {
    asm volatile("cp.async.wait_group %0;" :: "n"(N) : "memory");
}
__device__ __forceinline__ void ldsm4(uint32_t* r, uint32_t addr) {
    asm volatile("ldmatrix.sync.aligned.m8n8.x4.shared.b16 {%0,%1,%2,%3}, [%4];"
                 : "=r"(r[0]), "=r"(r[1]), "=r"(r[2]), "=r"(r[3]) : "r"(addr));
}
__device__ __forceinline__ void mma_fp16(float* c, const uint32_t* a, const uint32_t* b) {
    asm volatile(
        "mma.sync.aligned.m16n8k16.row.col.f32.f16.f16.f32 "
        "{%0,%1,%2,%3}, {%4,%5,%6,%7}, {%8,%9}, {%0,%1,%2,%3};"
        : "+f"(c[0]), "+f"(c[1]), "+f"(c[2]), "+f"(c[3])
        : "r"(a[0]), "r"(a[1]), "r"(a[2]), "r"(a[3]), "r"(b[0]), "r"(b[1]));
}
__device__ __forceinline__ uint32_t pack_h2(float lo, float hi) {
    __half2 h = __floats2half2_rn(lo, hi);
    return *(uint32_t*)&h;
}
__device__ __forceinline__ unsigned short f2h_bits(float v) {
    __half h = __float2half_rn(v);
    return *(unsigned short*)&h;
}

// ---------------------------------------------------------------------------
// fp32 -> fp16 cast (elementwise, vectorized)
// ---------------------------------------------------------------------------
__global__ void cast_h_kernel(const float* __restrict__ x,
                              unsigned short* __restrict__ h, int n4) {
    int i = blockIdx.x * blockDim.x + threadIdx.x;
    if (i >= n4) return;
    float4 v = ((const float4*)x)[i];
    ushort4 hh;
    hh.x = f2h_bits(v.x);
    hh.y = f2h_bits(v.y);
    hh.z = f2h_bits(v.z);
    hh.w = f2h_bits(v.w);
    ((ushort4*)h)[i] = hh;
}

// ---------------------------------------------------------------------------
// W[K x N] fp32 -> T[N x K] single fp16 (tiled transpose)
// ---------------------------------------------------------------------------
__global__ void transpose_h_kernel(const float* __restrict__ W,
                                   unsigned short* __restrict__ T,
                                   int K, int N) {
    __shared__ float t[32][33];
    int n0 = blockIdx.x * 32, k0 = blockIdx.y * 32;
    int tx = threadIdx.x, ty = threadIdx.y;  // 32 x 8
#pragma unroll
    for (int r = 0; r < 32; r += 8)
        t[ty + r][tx] = W[(size_t)(k0 + ty + r) * N + n0 + tx];
    __syncthreads();
#pragma unroll
    for (int r = 0; r < 32; r += 8) {
        size_t o = (size_t)(n0 + ty + r) * K + k0 + tx;
        T[o] = f2h_bits(t[tx][ty + r]);
    }
}

// ---------------------------------------------------------------------------
// V region of qkv -> transposed fp16 [dglob][s]
// ---------------------------------------------------------------------------
__global__ void vsplit_transpose_kernel(const float* __restrict__ qkv,
                                        unsigned short* __restrict__ Thi) {
    __shared__ float t[32][33];
    int d0 = blockIdx.x * 32, s0 = blockIdx.y * 32;
    int tx = threadIdx.x, ty = threadIdx.y;  // 32 x 8
#pragma unroll
    for (int r = 0; r < 32; r += 8)
        t[ty + r][tx] = qkv[(size_t)(s0 + ty + r) * QKV_N + 5120 + d0 + tx];
    __syncthreads();
#pragma unroll
    for (int r = 0; r < 32; r += 8) {
        size_t o = (size_t)(d0 + ty + r) * S_LEN + s0 + tx;
        Thi[o] = f2h_bits(t[tx][ty + r]);
    }
}

// ---------------------------------------------------------------------------
// RoPE + scale; Q and K both -> single fp16.
// ---------------------------------------------------------------------------
__global__ void rope_split_kernel(const float* __restrict__ qkv,
                                  const float* __restrict__ cosp,
                                  const float* __restrict__ sinp,
                                  unsigned short* __restrict__ qhi,
                                  unsigned short* __restrict__ khi) {
    int idx = blockIdx.x * blockDim.x + threadIdx.x;
    const int PAIRS = (D_MODEL + 1024) / 2;  // 2560 per row
    if (idx >= S_LEN * PAIRS) return;
    int s = idx / PAIRS;
    int pair = idx - s * PAIRS;
    int p = pair & 63;
    float c = cosp[s * 64 + p];
    float sn = sinp[s * 64 + p];
    bool isQ = pair < 2048;
    int col = isQ ? 2 * pair : 4096 + 2 * (pair - 2048);
    const float* src = qkv + (size_t)s * QKV_N + col;
    float t0 = src[0], t1 = src[1];
    float o0 = t0 * c - t1 * sn;
    float o1 = t0 * sn + t1 * c;
    if (isQ) {
        o0 *= QK_SCALE; o1 *= QK_SCALE;
        ushort2 hh = make_ushort2(f2h_bits(o0), f2h_bits(o1));
        *(ushort2*)(qhi + (size_t)s * D_MODEL + 2 * pair) = hh;
    } else {
        ushort2 hh = make_ushort2(f2h_bits(o0), f2h_bits(o1));
        *(ushort2*)(khi + (size_t)s * 1024 + 2 * (pair - 2048)) = hh;
    }
}

// ---------------------------------------------------------------------------
// Warp-MMA fp16 1-pass GEMM: C[M,N] = A[M,K] @ B[N,K]^T, both single fp16.
// CTA tile 128x128, BK=32, 8 warps, 2-stage cp.async, 2 CTAs/SM.
// Used for BOTH the QKV projection and the output projection.
// ---------------------------------------------------------------------------
#define G_BM 128
#define G_BN 128
#define G_BK 32
#define G_ROWB 80
#define G_TILE 10240
#define G_STAGE 20480        // A, B
#define G_SMEM (2 * G_STAGE)

__global__ __launch_bounds__(256, 2) void gemm1_mma_kernel(
    const unsigned short* __restrict__ A_, const unsigned short* __restrict__ B_,
    float* __restrict__ C, int M, int N, int K)
{
    extern __shared__ char smem[];
    uint32_t sb = cvta_shared(smem);
    const int tid = threadIdx.x;
    const int lane = tid & 31, wid = tid >> 5;
    const int warp_m = wid & 3;
    const int warp_n = wid >> 2;
    const int m0 = blockIdx.x * G_BM;
    const int n0 = blockIdx.y * G_BN;

    const unsigned short* srcs[2] = { A_ + (size_t)m0 * K, B_ + (size_t)n0 * K };

    auto load_stage = [&](int ch, int st) {
        uint32_t base = sb + st * G_STAGE;
        int k0 = ch * G_BK;
#pragma unroll
        for (int v = 0; v < 2; v++) {
            uint32_t tb = base + v * G_TILE;
            const unsigned short* src = srcs[v];
            for (int i = tid; i < 512; i += 256) {
                int row = i >> 2, c = i & 3;
                cp16(tb + row * G_ROWB + c * 16,
                     src + (size_t)row * K + k0 + c * 8);
            }
        }
        cp_commit();
    };

    float acc[2][8][4];
#pragma unroll
    for (int mt = 0; mt < 2; mt++)
#pragma unroll
        for (int nt = 0; nt < 8; nt++)
#pragma unroll
            for (int r = 0; r < 4; r++) acc[mt][nt][r] = 0.f;

    const int NC = K / G_BK;
    load_stage(0, 0);

    const uint32_t a_off = (uint32_t)((lane & 15) * G_ROWB + (lane >> 4) * 16);

    for (int ch = 0; ch < NC; ch++) {
        int st = ch & 1;
        if (ch + 1 < NC) { load_stage(ch + 1, st ^ 1); cp_wait<1>(); }
        else { cp_wait<0>(); }
        __syncthreads();

        uint32_t base = sb + st * G_STAGE;
        uint32_t aT = base + (warp_m * 32) * G_ROWB + a_off;
        uint32_t bT = base + G_TILE + (warp_n * 64) * G_ROWB + a_off;

#pragma unroll
        for (int k16 = 0; k16 < 2; k16++) {
            uint32_t koff = k16 * 32;
            uint32_t am[2][4];
#pragma unroll
            for (int mt = 0; mt < 2; mt++)
                ldsm4(am[mt], aT + mt * 16 * G_ROWB + koff);
            uint32_t bh[8][2];
#pragma unroll
            for (int ng = 0; ng < 4; ng++) {
                uint32_t r[4];
                ldsm4(r, bT + ng * 16 * G_ROWB + koff);
                bh[2 * ng][0] = r[0]; bh[2 * ng][1] = r[2];
                bh[2 * ng + 1][0] = r[1]; bh[2 * ng + 1][1] = r[3];
            }
#pragma unroll
            for (int mt = 0; mt < 2; mt++)
#pragma unroll
                for (int nt = 0; nt < 8; nt++)
                    mma_fp16(acc[mt][nt], am[mt], bh[nt]);
        }
        __syncthreads();
    }

#pragma unroll
    for (int mt = 0; mt < 2; mt++) {
        int row = m0 + warp_m * 32 + mt * 16 + (lane >> 2);
#pragma unroll
        for (int nt = 0; nt < 8; nt++) {
            int col = n0 + warp_n * 64 + nt * 8 + (lane & 3) * 2;
            *(float2*)&C[(size_t)row * N + col] =
                make_float2(acc[mt][nt][0], acc[mt][nt][1]);
            *(float2*)&C[(size_t)(row + 8) * N + col] =
                make_float2(acc[mt][nt][2], acc[mt][nt][3]);
        }
    }
}

// ---------------------------------------------------------------------------
// Tensor-core flash attention v9 (causal, GQA 4:1), all fp16 1-pass MMA.
// KV tile 64; 128 thr, 64 q-rows, 2-stage; smem 89088 B -> 2 CTAs/SM.
// (unchanged from R16 — 1172-proven)
// ---------------------------------------------------------------------------
#define A9_QROW 272      // 128 halfs * 2B + 16B pad
#define A9_VROW 144      // 64 halfs * 2B + 16B pad
#define A9_Q 0
#define A9_ST0 17408     // 64 * 272
#define A9_K 0
#define A9_V 17408       // 64 rows * 272
#define A9_STAGE_SZ 35840   // 17408 + 128*144
#define A9_SMEM (A9_ST0 + 2 * A9_STAGE_SZ)   // 89088 B -> 2 CTAs/SM

__global__ __launch_bounds__(128, 2) void attn_mma_kernel(
    const unsigned short* __restrict__ Qhi,
    const unsigned short* __restrict__ Khi,
    const unsigned short* __restrict__ Vthi,
    unsigned short* __restrict__ atthi)
{
    extern __shared__ char smem[];
    uint32_t sb = cvta_shared(smem);
    const int tid = threadIdx.x;
    const int lane = tid & 31, wid = tid >> 5;          // 4 warps
    const int qblk = gridDim.x - 1 - blockIdx.x;        // heavy blocks first
    const int h = blockIdx.y;
    const int kvh = h >> 2;
    const int q0 = qblk * 64;
    const int wr = wid * 16;                            // warp rows 0..63
    const int g = lane >> 2;
    const int t4 = lane & 3;

    // ---- Q tile load (once): 64 rows x 128 halfs, single fp16 ----
    {
        const unsigned short* qsrc = Qhi + (size_t)q0 * D_MODEL + h * 128;
        for (int i = tid; i < 1024; i += 128) {
            int row = i >> 4, c = i & 15;
            cp16(sb + A9_Q + row * A9_QROW + c * 16,
                 qsrc + (size_t)row * D_MODEL + c * 8);
        }
        cp_commit();
    }

    const unsigned short* ksrc = Khi + kvh * 128;
    const unsigned short* vsrc = Vthi + (size_t)kvh * 128 * S_LEN;

    auto load_tile = [&](int j, int st) {
        uint32_t base = sb + A9_ST0 + st * A9_STAGE_SZ;
        int kv0 = j * 64;
        // K: 64 rows x 256B (fp16)
        for (int i = tid; i < 1024; i += 128) {
            int row = i >> 4, c = i & 15;
            cp16(base + A9_K + row * A9_QROW + c * 16,
                 ksrc + (size_t)(kv0 + row) * 1024 + c * 8);
        }
        // V: 128 d-rows x 128B (fp16, 64 kv cols)
        for (int i = tid; i < 1024; i += 128) {
            int row = i >> 3, c = i & 7;
            cp16(base + A9_V + row * A9_VROW + c * 16,
                 vsrc + (size_t)row * S_LEN + kv0 + c * 8);
        }
        cp_commit();
    };

    const int ntiles = qblk + 1;
    load_tile(0, 0);
    cp_wait<1>();          // Q group done (only tile0 outstanding)
    __syncthreads();

    // ---- hoist Q fragments into registers (16 rows x 128 K per warp) ----
    const uint32_t lmoff = (uint32_t)((lane & 15) * A9_QROW + (lane >> 4) * 16);
    uint32_t aq[8][4];
    {
        uint32_t qh = sb + A9_Q + wr * A9_QROW + lmoff;
#pragma unroll
        for (int kk = 0; kk < 8; kk++) ldsm4(aq[kk], qh + kk * 32);
    }

    float o[16][4];
#pragma unroll
    for (int nt = 0; nt < 16; nt++)
#pragma unroll
        for (int r = 0; r < 4; r++) o[nt][r] = 0.f;
    float m0 = -1e30f, m1 = -1e30f, l0 = 0.f, l1 = 0.f;

    const uint32_t vmoff = (uint32_t)((lane & 15) * A9_VROW + (lane >> 4) * 16);

    for (int j = 0; j < ntiles; j++) {
        int st = j & 1;
        __syncthreads();   // all warps done reading buffer st^1 (iter j-1)
        if (j + 1 < ntiles) { load_tile(j + 1, st ^ 1); cp_wait<1>(); }
        else { cp_wait<0>(); }
        __syncthreads();

        uint32_t base = sb + A9_ST0 + st * A9_STAGE_SZ;
        uint32_t kB = base + A9_K + lmoff;

        // ---- S = Q @ K^T (single-pass fp16), 16 rows x 64 cols / warp ----
        float sacc[8][4];
#pragma unroll
        for (int nt = 0; nt < 8; nt++)
#pragma unroll
            for (int r = 0; r < 4; r++) sacc[nt][r] = 0.f;

#pragma unroll
        for (int kk = 0; kk < 8; kk++) {
#pragma unroll
            for (int ng = 0; ng < 4; ng++) {
                uint32_t rh[4];
                ldsm4(rh, kB + ng * 16 * A9_QROW + kk * 32);
                uint32_t b0[2] = { rh[0], rh[2] }, b1[2] = { rh[1], rh[3] };
                mma_fp16(sacc[2 * ng],     aq[kk], b0);
                mma_fp16(sacc[2 * ng + 1], aq[kk], b1);
            }
        }

        // ---- causal mask (diagonal tile only: j == qblk) ----
        if (j == qblk) {
            int r0 = q0 + wr + g, r1 = r0 + 8;
            int cb = j * 64 + 2 * t4;
#pragma unroll
            for (int nt = 0; nt < 8; nt++) {
                int c0 = cb + nt * 8, c1 = c0 + 1;
                if (c0 > r0) sacc[nt][0] = -1e30f;
                if (c1 > r0) sacc[nt][1] = -1e30f;
                if (c0 > r1) sacc[nt][2] = -1e30f;
                if (c1 > r1) sacc[nt][3] = -1e30f;
            }
        }

        // ---- online softmax (once per 64 kv) ----
        float mx0 = -1e30f, mx1 = -1e30f;
#pragma unroll
        for (int nt = 0; nt < 8; nt++) {
            mx0 = fmaxf(mx0, fmaxf(sacc[nt][0], sacc[nt][1]));
            mx1 = fmaxf(mx1, fmaxf(sacc[nt][2], sacc[nt][3]));
        }
        mx0 = fmaxf(mx0, __shfl_xor_sync(0xffffffffu, mx0, 1));
        mx0 = fmaxf(mx0, __shfl_xor_sync(0xffffffffu, mx0, 2));
        mx1 = fmaxf(mx1, __shfl_xor_sync(0xffffffffu, mx1, 1));
        mx1 = fmaxf(mx1, __shfl_xor_sync(0xffffffffu, mx1, 2));
        float mn0 = fmaxf(m0, mx0), mn1 = fmaxf(m1, mx1);
        float sc0 = __expf(m0 - mn0), sc1 = __expf(m1 - mn1);
        m0 = mn0; m1 = mn1;
        float sum0 = 0.f, sum1 = 0.f;
#pragma unroll
        for (int nt = 0; nt < 8; nt++) {
            sacc[nt][0] = __expf(sacc[nt][0] - mn0);
            sacc[nt][1] = __expf(sacc[nt][1] - mn0);
            sacc[nt][2] = __expf(sacc[nt][2] - mn1);
            sacc[nt][3] = __expf(sacc[nt][3] - mn1);
            sum0 += sacc[nt][0] + sacc[nt][1];
            sum1 += sacc[nt][2] + sacc[nt][3];
        }
        sum0 += __shfl_xor_sync(0xffffffffu, sum0, 1);
        sum0 += __shfl_xor_sync(0xffffffffu, sum0, 2);
        sum1 += __shfl_xor_sync(0xffffffffu, sum1, 1);
        sum1 += __shfl_xor_sync(0xffffffffu, sum1, 2);
        l0 = l0 * sc0 + sum0;
        l1 = l1 * sc1 + sum1;
#pragma unroll
        for (int nt = 0; nt < 16; nt++) {
            o[nt][0] *= sc0; o[nt][1] *= sc0;
            o[nt][2] *= sc1; o[nt][3] *= sc1;
        }

        // ---- O += P @ V (single-pass fp16), K-dim = 64 ----
        uint32_t vB = base + A9_V + vmoff;
#pragma unroll
        for (int kk2 = 0; kk2 < 4; kk2++) {
            uint32_t aph[4];
            aph[0] = pack_h2(sacc[2 * kk2][0],     sacc[2 * kk2][1]);
            aph[1] = pack_h2(sacc[2 * kk2][2],     sacc[2 * kk2][3]);
            aph[2] = pack_h2(sacc[2 * kk2 + 1][0], sacc[2 * kk2 + 1][1]);
            aph[3] = pack_h2(sacc[2 * kk2 + 1][2], sacc[2 * kk2 + 1][3]);
#pragma unroll
            for (int ng = 0; ng < 8; ng++) {
                uint32_t rv[4];
                ldsm4(rv, vB + ng * 16 * A9_VROW + kk2 * 32);
                uint32_t b0[2] = { rv[0], rv[2] }, b1[2] = { rv[1], rv[3] };
                mma_fp16(o[2 * ng],     aph, b0);
                mma_fp16(o[2 * ng + 1], aph, b1);
            }
        }
    }

    // ---- finalize: O /= l, write single fp16 ----
    float inv0 = 1.f / l0, inv1 = 1.f / l1;
    int row0 = q0 + wr + g;
    size_t ob0 = (size_t)row0 * D_MODEL + h * 128 + 2 * t4;
    size_t ob1 = (size_t)(row0 + 8) * D_MODEL + h * 128 + 2 * t4;
#pragma unroll
    for (int nt = 0; nt < 16; nt++) {
        ushort2 hh0 = make_ushort2(f2h_bits(o[nt][0] * inv0), f2h_bits(o[nt][1] * inv0));
        ushort2 hh1 = make_ushort2(f2h_bits(o[nt][2] * inv1), f2h_bits(o[nt][3] * inv1));
        *(ushort2*)(atthi + ob0 + nt * 8) = hh0;
        *(ushort2*)(atthi + ob1 + nt * 8) = hh1;
    }
}

// ---------------------------------------------------------------------------
// Launch
// ---------------------------------------------------------------------------
extern "C" void kernel_launch(void* const* d_in, const int* in_sizes, int n_in,
                              void* d_out, int out_size)
{
    const float* x    = (const float*)d_in[0];
    const float* wq   = (const float*)d_in[1];
    const float* wk   = (const float*)d_in[2];
    const float* wv   = (const float*)d_in[3];
    const float* wo   = (const float*)d_in[4];
    const float* cosp = (const float*)d_in[5];
    const float* sinp = (const float*)d_in[6];

    unsigned short *xh, *wqkvT, *woT;
    unsigned short *qhi, *khi, *vthi, *atthi;
    float *qkv;
    cudaGetSymbolAddress((void**)&xh, g_xh);
    cudaGetSymbolAddress((void**)&wqkvT, g_wqkvT);
    cudaGetSymbolAddress((void**)&woT, g_woT);
    cudaGetSymbolAddress((void**)&qhi, g_qhi);
    cudaGetSymbolAddress((void**)&khi, g_khi);
    cudaGetSymbolAddress((void**)&vthi, g_vthi);
    cudaGetSymbolAddress((void**)&atthi, g_atthi);
    cudaGetSymbolAddress((void**)&qkv, g_qkv);

    cudaFuncSetAttribute(gemm1_mma_kernel, cudaFuncAttributeMaxDynamicSharedMemorySize, G_SMEM);
    cudaFuncSetAttribute(attn_mma_kernel, cudaFuncAttributeMaxDynamicSharedMemorySize, A9_SMEM);

    dim3 tb(32, 8);

    // 1) Cast x -> fp16
    {
        int n4 = S_LEN * D_MODEL / 4;
        cast_h_kernel<<<(n4 + 255) / 256, 256>>>(x, xh, n4);
    }
    // 2-4) QKV weight transposes (single fp16)
    transpose_h_kernel<<<dim3(D_MODEL / 32, D_MODEL / 32), tb>>>(
        wq, wqkvT, D_MODEL, D_MODEL);
    transpose_h_kernel<<<dim3(1024 / 32, D_MODEL / 32), tb>>>(
        wk, wqkvT + (size_t)4096 * D_MODEL, D_MODEL, 1024);
    transpose_h_kernel<<<dim3(1024 / 32, D_MODEL / 32), tb>>>(
        wv, wqkvT + (size_t)5120 * D_MODEL, D_MODEL, 1024);

    // 5) Fused QKV projection (fp16 1-pass)
    gemm1_mma_kernel<<<dim3(S_LEN / G_BM, QKV_N / G_BN), 256, G_SMEM>>>(
        xh, wqkvT, qkv, S_LEN, QKV_N, D_MODEL);

    // 6-7) RoPE (Q,K single fp16); transpose V (fp16)
    {
        int tot = S_LEN * 2560;
        rope_split_kernel<<<(tot + 255) / 256, 256>>>(qkv, cosp, sinp, qhi, khi);
        vsplit_transpose_kernel<<<dim3(1024 / 32, S_LEN / 32), tb>>>(qkv, vthi);
    }

    // 8) wo transpose (single fp16)
    transpose_h_kernel<<<dim3(D_MODEL / 32, D_MODEL / 32), tb>>>(
        wo, woT, D_MODEL, D_MODEL);

    // 9) Tensor-core flash attention v9 (KV=64, fp16 out)
    attn_mma_kernel<<<dim3(S_LEN / 64, N_HEADS), 128, A9_SMEM>>>(
        qhi, khi, vthi, atthi);

    // 10) Output projection -> d_out (fp16 1-pass)
    gemm1_mma_kernel<<<dim3(S_LEN / G_BM, D_MODEL / G_BN), 256, G_SMEM>>>(
        atthi, woT, (float*)d_out, S_LEN, D_MODEL, D_MODEL);
}